// round 5
// baseline (speedup 1.0000x reference)
#include <cuda_runtime.h>
#include <cuda_fp16.h>
#include <math.h>
#include <stdint.h>

// Problem shape constants
#define BATCH 8
#define NX    2048
#define MMEM  256
#define TT    2304          // NX + MMEM
#define DD    512
#define D3    1536          // 3*DD

// Scratch (allocation-free: __device__ globals)
__device__ __half g_XM [(size_t)BATCH * TT * DD];   // 18.9 MB fp16
__device__ __half g_W  [(size_t)D3 * DD];           //  1.5 MB fp16
__device__ __half g_QKV[(size_t)BATCH * TT * D3];   // 56.6 MB fp16
__device__ float  g_S  [(size_t)BATCH * TT * TT];   // 169.9 MB fp32 logits
__device__ __half g_P  [(size_t)BATCH * TT * TT];   // 85.0 MB fp16 probs

// ---------------------------------------------------------------------------
// PTX helpers
// ---------------------------------------------------------------------------
__device__ __forceinline__ void mma_f16(float* c, const uint32_t* a, const uint32_t* b) {
    asm volatile(
        "mma.sync.aligned.m16n8k16.row.col.f32.f16.f16.f32 "
        "{%0,%1,%2,%3}, {%4,%5,%6,%7}, {%8,%9}, {%0,%1,%2,%3};\n"
        : "+f"(c[0]), "+f"(c[1]), "+f"(c[2]), "+f"(c[3])
        : "r"(a[0]), "r"(a[1]), "r"(a[2]), "r"(a[3]), "r"(b[0]), "r"(b[1]));
}

__device__ __forceinline__ void ldsm4(uint32_t* r, uint32_t addr) {
    asm volatile("ldmatrix.sync.aligned.m8n8.x4.shared.b16 {%0,%1,%2,%3}, [%4];"
                 : "=r"(r[0]), "=r"(r[1]), "=r"(r[2]), "=r"(r[3]) : "r"(addr));
}

__device__ __forceinline__ void ldsm4t(uint32_t* r, uint32_t addr) {
    asm volatile("ldmatrix.sync.aligned.m8n8.x4.trans.shared.b16 {%0,%1,%2,%3}, [%4];"
                 : "=r"(r[0]), "=r"(r[1]), "=r"(r[2]), "=r"(r[3]) : "r"(addr));
}

__device__ __forceinline__ void cpasync16(uint32_t s, const void* g) {
    asm volatile("cp.async.cg.shared.global [%0], [%1], 16;\n" :: "r"(s), "l"(g));
}
__device__ __forceinline__ void cp_commit() {
    asm volatile("cp.async.commit_group;\n" ::: "memory");
}
__device__ __forceinline__ void cp_wait0() {
    asm volatile("cp.async.wait_group 0;\n" ::: "memory");
}

// ---------------------------------------------------------------------------
// Input prep: XM = concat(x, mem^T) in fp16;  W -> fp16
// ---------------------------------------------------------------------------
__global__ void build_xm_half(const float* __restrict__ x,
                              const float* __restrict__ mem) {
    size_t idx = (size_t)blockIdx.x * blockDim.x + threadIdx.x;
    const size_t total = (size_t)BATCH * TT * DD;
    if (idx >= total) return;
    int d = (int)(idx % DD);
    size_t bt = idx / DD;
    int t = (int)(bt % TT);
    int b = (int)(bt / TT);
    float v;
    if (t < NX) v = x[((size_t)b * NX + t) * DD + d];
    else        v = mem[(size_t)d * MMEM + (t - NX)];   // mem[0, d, t-NX]
    g_XM[idx] = __float2half(v);
}

__global__ void cvt_w_half(const float* __restrict__ w) {
    size_t idx = (size_t)blockIdx.x * blockDim.x + threadIdx.x;
    if (idx < (size_t)D3 * DD) g_W[idx] = __float2half(w[idx]);
}

// ---------------------------------------------------------------------------
// NT GEMM: C[m,n] = alpha * sum_k A[m*lda+k] * B[n*ldb+k]
// CTA 128x128, 4 warps (2m x 2n), warp tile 64x64, BK=32.
// cp.async double-buffered smem [m][k]/[n][k], padded stride 40 halves.
// ---------------------------------------------------------------------------
#define NTS 40

template <typename CT>
__global__ __launch_bounds__(128)
void gemm_nt_f16(const __half* __restrict__ A, const __half* __restrict__ B,
                 CT* __restrict__ C, int Kdim,
                 int lda, int ldb, int ldc, float alpha,
                 size_t sA, size_t sB, size_t sC) {
    A += (size_t)blockIdx.z * sA;
    B += (size_t)blockIdx.z * sB;
    C += (size_t)blockIdx.z * sC;
    const int m0 = blockIdx.y * 128;
    const int n0 = blockIdx.x * 128;
    const int tid = threadIdx.x;
    const int lane = tid & 31;
    const int wid = tid >> 5;
    const int mBase = (wid & 1) * 64;
    const int nBase = (wid >> 1) * 64;

    __shared__ __half As[2][128 * NTS];
    __shared__ __half Bs[2][128 * NTS];
    const uint32_t aSm = (uint32_t)__cvta_generic_to_shared(&As[0][0]);
    const uint32_t bSm = (uint32_t)__cvta_generic_to_shared(&Bs[0][0]);
    const uint32_t stB = 128 * NTS * 2;   // stage stride bytes

    // global->smem: thread t owns row t of both tiles, 4x 16B chunks
    const __half* Ag = A + (size_t)(m0 + tid) * lda;
    const __half* Bg = B + (size_t)(n0 + tid) * ldb;
    const uint32_t aStore = aSm + tid * (NTS * 2);
    const uint32_t bStore = bSm + tid * (NTS * 2);

    // ldmatrix lane bases (bytes)
    const uint32_t aFrag = aSm + ((mBase + (lane & 15)) * NTS + 8 * (lane >> 4)) * 2;
    const uint32_t bFrag = bSm + ((nBase + (lane & 15)) * NTS + 8 * (lane >> 4)) * 2;

    float acc[4][8][4] = {};

    // prologue: stage 0
#pragma unroll
    for (int c = 0; c < 4; c++) {
        cpasync16(aStore + c * 16, Ag + c * 8);
        cpasync16(bStore + c * 16, Bg + c * 8);
    }
    cp_commit();

    const int nIter = Kdim >> 5;
    for (int t = 0; t < nIter; t++) {
        cp_wait0();
        __syncthreads();
        if (t + 1 < nIter) {
            const int st = (t + 1) & 1;
            const int k0 = (t + 1) * 32;
#pragma unroll
            for (int c = 0; c < 4; c++) {
                cpasync16(aStore + st * stB + c * 16, Ag + k0 + c * 8);
                cpasync16(bStore + st * stB + c * 16, Bg + k0 + c * 8);
            }
            cp_commit();
        }
        const uint32_t aO = aFrag + (t & 1) * stB;
        const uint32_t bO = bFrag + (t & 1) * stB;
#pragma unroll
        for (int s = 0; s < 2; s++) {
            uint32_t af[4][4], bf[4][4];
#pragma unroll
            for (int mi = 0; mi < 4; mi++)
                ldsm4(af[mi], aO + (mi * 16 * NTS + s * 16) * 2);
#pragma unroll
            for (int u = 0; u < 4; u++)
                ldsm4(bf[u], bO + (u * 16 * NTS + s * 16) * 2);
#pragma unroll
            for (int mi = 0; mi < 4; mi++)
#pragma unroll
                for (int ni = 0; ni < 8; ni++) {
                    // x4 regs: r0=(n+0,k0) r1=(n+8,k0) r2=(n+0,k8) r3=(n+8,k8)
                    uint32_t bb[2] = { bf[ni >> 1][ni & 1], bf[ni >> 1][(ni & 1) + 2] };
                    mma_f16(acc[mi][ni], af[mi], bb);
                }
        }
    }

    const int g = lane >> 2, tg = lane & 3;
#pragma unroll
    for (int mi = 0; mi < 4; mi++) {
        int r0 = m0 + mBase + mi * 16 + g;
#pragma unroll
        for (int ni = 0; ni < 8; ni++) {
            int cb = n0 + nBase + ni * 8 + 2 * tg;
            if constexpr (sizeof(CT) == 2) {
                __half2 v0 = __floats2half2_rn(alpha * acc[mi][ni][0], alpha * acc[mi][ni][1]);
                __half2 v1 = __floats2half2_rn(alpha * acc[mi][ni][2], alpha * acc[mi][ni][3]);
                *reinterpret_cast<__half2*>((__half*)C + (size_t)r0 * ldc + cb) = v0;
                *reinterpret_cast<__half2*>((__half*)C + (size_t)(r0 + 8) * ldc + cb) = v1;
            } else {
                float2 v0 = make_float2(alpha * acc[mi][ni][0], alpha * acc[mi][ni][1]);
                float2 v1 = make_float2(alpha * acc[mi][ni][2], alpha * acc[mi][ni][3]);
                *reinterpret_cast<float2*>((float*)C + (size_t)r0 * ldc + cb) = v0;
                *reinterpret_cast<float2*>((float*)C + (size_t)(r0 + 8) * ldc + cb) = v1;
            }
        }
    }
}

// ---------------------------------------------------------------------------
// TN GEMM: C[m,n] = alpha * sum_k A[k*lda+m] * B[k*ldb+n], C fp32.
// CTA 128x128, 4 warps (2x2), warp tile 64x64, BK=32.
// cp.async double-buffered smem [k][m]/[k][n], stride 136 halves; ldmatrix.trans.
// ---------------------------------------------------------------------------
#define TNS 136

__global__ __launch_bounds__(128)
void gemm_tn_f16(const __half* __restrict__ A, const __half* __restrict__ B,
                 float* __restrict__ C, int Kdim,
                 int lda, int ldb, int ldc, float alpha,
                 size_t sA, size_t sB, size_t sC) {
    A += (size_t)blockIdx.z * sA;
    B += (size_t)blockIdx.z * sB;
    C += (size_t)blockIdx.z * sC;
    const int m0 = blockIdx.y * 128;
    const int n0 = blockIdx.x * 128;
    const int tid = threadIdx.x;
    const int lane = tid & 31;
    const int wid = tid >> 5;
    const int mBase = (wid & 1) * 64;
    const int nBase = (wid >> 1) * 64;

    __shared__ __half As[2][32 * TNS];
    __shared__ __half Bs[2][32 * TNS];
    const uint32_t aSm = (uint32_t)__cvta_generic_to_shared(&As[0][0]);
    const uint32_t bSm = (uint32_t)__cvta_generic_to_shared(&Bs[0][0]);
    const uint32_t stB = 32 * TNS * 2;

    // global->smem: thread t owns k-row (t>>2), 4x 16B chunks at col (t&3)*32
    const int kr = tid >> 2;
    const int c0 = (tid & 3) * 32;
    const __half* Ag = A + m0 + c0;
    const __half* Bg = B + n0 + c0;
    const uint32_t aStore = aSm + (kr * TNS + c0) * 2;
    const uint32_t bStore = bSm + (kr * TNS + c0) * 2;

    // trans-ldmatrix lane bases (bytes)
    // A frags: matrices (k0,m0),(k0,m8),(k8,m0),(k8,m8)
    const uint32_t aFrag = aSm +
        (((lane & 7) + 8 * (lane >> 4)) * TNS + mBase + 8 * ((lane >> 3) & 1)) * 2;
    // B frags: matrices (k0,n0),(k8,n0),(k0,n8),(k8,n8)
    const uint32_t bFrag = bSm +
        (((lane & 7) + 8 * ((lane >> 3) & 1)) * TNS + nBase + 8 * (lane >> 4)) * 2;

    float acc[4][8][4] = {};

    // prologue: stage 0
#pragma unroll
    for (int c = 0; c < 4; c++) {
        cpasync16(aStore + c * 16, Ag + (size_t)kr * lda + c * 8);
        cpasync16(bStore + c * 16, Bg + (size_t)kr * ldb + c * 8);
    }
    cp_commit();

    const int nIter = Kdim >> 5;
    for (int t = 0; t < nIter; t++) {
        cp_wait0();
        __syncthreads();
        if (t + 1 < nIter) {
            const int st = (t + 1) & 1;
            const size_t gk = (size_t)((t + 1) * 32 + kr);
#pragma unroll
            for (int c = 0; c < 4; c++) {
                cpasync16(aStore + st * stB + c * 16, Ag + gk * lda + c * 8);
                cpasync16(bStore + st * stB + c * 16, Bg + gk * ldb + c * 8);
            }
            cp_commit();
        }
        const uint32_t aO = aFrag + (t & 1) * stB;
        const uint32_t bO = bFrag + (t & 1) * stB;
#pragma unroll
        for (int s = 0; s < 2; s++) {
            uint32_t af[4][4], bf[4][4];
#pragma unroll
            for (int mi = 0; mi < 4; mi++)
                ldsm4t(af[mi], aO + (s * 16 * TNS + mi * 16) * 2);
#pragma unroll
            for (int u = 0; u < 4; u++)
                ldsm4t(bf[u], bO + (s * 16 * TNS + u * 16) * 2);
#pragma unroll
            for (int mi = 0; mi < 4; mi++)
#pragma unroll
                for (int ni = 0; ni < 8; ni++) {
                    // x4 regs: r0=(k0,n+0) r1=(k8,n+0) r2=(k0,n+8) r3=(k8,n+8)
                    uint32_t bb[2] = { bf[ni >> 1][2 * (ni & 1)], bf[ni >> 1][2 * (ni & 1) + 1] };
                    mma_f16(acc[mi][ni], af[mi], bb);
                }
        }
    }

    const int g = lane >> 2, tg = lane & 3;
#pragma unroll
    for (int mi = 0; mi < 4; mi++) {
        int r0 = m0 + mBase + mi * 16 + g;
#pragma unroll
        for (int ni = 0; ni < 8; ni++) {
            int cb = n0 + nBase + ni * 8 + 2 * tg;
            float2 v0 = make_float2(alpha * acc[mi][ni][0], alpha * acc[mi][ni][1]);
            float2 v1 = make_float2(alpha * acc[mi][ni][2], alpha * acc[mi][ni][3]);
            *reinterpret_cast<float2*>(C + (size_t)r0 * ldc + cb) = v0;
            *reinterpret_cast<float2*>(C + (size_t)(r0 + 8) * ldc + cb) = v1;
        }
    }
}

// ---------------------------------------------------------------------------
// Row softmax over T=2304 columns: read fp32 logits, write fp16 probs.
// ---------------------------------------------------------------------------
__global__ __launch_bounds__(256)
void softmax_rows_kernel(const float* __restrict__ S, __half* __restrict__ P) {
    const float* row = S + (size_t)blockIdx.x * TT;
    __half* prow = P + (size_t)blockIdx.x * TT;
    const int tid = threadIdx.x;
    __shared__ float red[8];

    float v[9];
    float lmax = -1e30f;
#pragma unroll
    for (int it = 0; it < 9; it++) {
        v[it] = row[tid + it * 256];
        lmax = fmaxf(lmax, v[it]);
    }
#pragma unroll
    for (int o = 16; o; o >>= 1)
        lmax = fmaxf(lmax, __shfl_xor_sync(0xffffffffu, lmax, o));
    if ((tid & 31) == 0) red[tid >> 5] = lmax;
    __syncthreads();
    float m = red[0];
#pragma unroll
    for (int w = 1; w < 8; w++) m = fmaxf(m, red[w]);

    float e[9];
    float lsum = 0.f;
#pragma unroll
    for (int it = 0; it < 9; it++) {
        e[it] = __expf(v[it] - m);
        lsum += e[it];
    }
#pragma unroll
    for (int o = 16; o; o >>= 1)
        lsum += __shfl_xor_sync(0xffffffffu, lsum, o);
    __syncthreads();
    if ((tid & 31) == 0) red[tid >> 5] = lsum;
    __syncthreads();
    float Z = 0.f;
#pragma unroll
    for (int w = 0; w < 8; w++) Z += red[w];
    float inv = 1.0f / Z;
#pragma unroll
    for (int it = 0; it < 9; it++)
        prow[tid + it * 256] = __float2half(e[it] * inv);
}

// ---------------------------------------------------------------------------
// Launch: XM/W fp16 -> QKV -> S = Q K^T/sqrt(D) -> softmax -> out = P^T V
// ---------------------------------------------------------------------------
extern "C" void kernel_launch(void* const* d_in, const int* in_sizes, int n_in,
                              void* d_out, int out_size) {
    (void)in_sizes; (void)n_in; (void)out_size;
    const float* x   = (const float*)d_in[0];
    const float* mem = (const float*)d_in[1];
    const float* w   = (const float*)d_in[2];
    float* out = (float*)d_out;

    __half *XM = nullptr, *W = nullptr, *QKV = nullptr, *P = nullptr;
    float *S = nullptr;
    cudaGetSymbolAddress((void**)&XM,  g_XM);
    cudaGetSymbolAddress((void**)&W,   g_W);
    cudaGetSymbolAddress((void**)&QKV, g_QKV);
    cudaGetSymbolAddress((void**)&S,   g_S);
    cudaGetSymbolAddress((void**)&P,   g_P);

    // 1) prep fp16 inputs
    {
        size_t total = (size_t)BATCH * TT * DD;
        build_xm_half<<<(unsigned)((total + 255) / 256), 256>>>(x, mem);
        size_t wtot = (size_t)D3 * DD;
        cvt_w_half<<<(unsigned)((wtot + 255) / 256), 256>>>(w);
    }
    // 2) QKV = XM @ W^T   (M = 18432, N = 1536, K = 512), fp16 out
    {
        dim3 grid(D3 / 128, (BATCH * TT) / 128, 1);
        gemm_nt_f16<__half><<<grid, 128>>>(XM, W, QKV, DD,
                                           DD, DD, D3, 1.0f, 0, 0, 0);
    }
    // 3) S[b,j,i] = Q[b,j,:] . K[b,i,:] / sqrt(D), fp32 out (2304 x 2304 x8)
    {
        dim3 grid(TT / 128, TT / 128, BATCH);
        const float scale = 0.044194173824159216f;  // 1/sqrt(512)
        gemm_nt_f16<float><<<grid, 128>>>(QKV, QKV + DD, S, DD,
                                          D3, D3, TT, scale,
                                          (size_t)TT * D3, (size_t)TT * D3,
                                          (size_t)TT * TT);
    }
    // 4) row softmax: fp32 S -> fp16 P
    softmax_rows_kernel<<<BATCH * TT, 256>>>(S, P);
    // 5) out[b,i,d] = sum_j P[b,j,i] * V[b,j,d]   (TN, fp32 out)
    {
        dim3 grid(DD / 128, TT / 128, BATCH);
        gemm_tn_f16<<<grid, 128>>>(P, QKV + 2 * DD, out, TT,
                                   TT, D3, DD, 1.0f,
                                   (size_t)TT * TT, (size_t)TT * D3,
                                   (size_t)TT * DD);
    }
}

// round 8
// speedup vs baseline: 1.0306x; 1.0306x over previous
#include <cuda_runtime.h>
#include <cuda_fp16.h>
#include <math.h>
#include <stdint.h>

// Problem shape constants
#define BATCH 8
#define NX    2048
#define MMEM  256
#define TT    2304          // NX + MMEM
#define DD    512
#define D3    1536          // 3*DD

// Scratch (allocation-free: __device__ globals, 128B-aligned)
__device__ __align__(128) __half g_XM [(size_t)BATCH * TT * DD];   // 18.9 MB
__device__ __align__(128) __half g_W  [(size_t)D3 * DD];           //  1.5 MB
__device__ __align__(128) __half g_QKV[(size_t)BATCH * TT * D3];   // 56.6 MB
__device__ __align__(128) float  g_S  [(size_t)BATCH * TT * TT];   // 169.9 MB  S'[i,j]
__device__ __align__(128) __half g_P  [(size_t)BATCH * TT * TT];   // 85.0 MB   P'[i,j]
__device__ __align__(128) __half g_VT [(size_t)BATCH * DD * TT];   // 18.9 MB   V^T

// ---------------------------------------------------------------------------
// PTX helpers (sm_100 base ISA only: mma.sync / ldmatrix / cp.async)
// ---------------------------------------------------------------------------
__device__ __forceinline__ void mma_f16(float* c, const uint32_t* a, const uint32_t* b) {
    asm volatile(
        "mma.sync.aligned.m16n8k16.row.col.f32.f16.f16.f32 "
        "{%0,%1,%2,%3}, {%4,%5,%6,%7}, {%8,%9}, {%0,%1,%2,%3};\n"
        : "+f"(c[0]), "+f"(c[1]), "+f"(c[2]), "+f"(c[3])
        : "r"(a[0]), "r"(a[1]), "r"(a[2]), "r"(a[3]), "r"(b[0]), "r"(b[1]));
}

__device__ __forceinline__ void ldsm4(uint32_t* r, uint32_t addr) {
    asm volatile("ldmatrix.sync.aligned.m8n8.x4.shared.b16 {%0,%1,%2,%3}, [%4];"
                 : "=r"(r[0]), "=r"(r[1]), "=r"(r[2]), "=r"(r[3]) : "r"(addr));
}

__device__ __forceinline__ void cpasync16(uint32_t s, const void* g) {
    asm volatile("cp.async.cg.shared.global [%0], [%1], 16;\n" :: "r"(s), "l"(g));
}
__device__ __forceinline__ void cp_commit() {
    asm volatile("cp.async.commit_group;\n" ::: "memory");
}
__device__ __forceinline__ void cp_wait0() {
    asm volatile("cp.async.wait_group 0;\n" ::: "memory");
}

// ---------------------------------------------------------------------------
// Input prep: XM = concat(x, mem^T) in fp16;  W -> fp16
// ---------------------------------------------------------------------------
__global__ void build_xm_half(const float* __restrict__ x,
                              const float* __restrict__ mem) {
    size_t idx = (size_t)blockIdx.x * blockDim.x + threadIdx.x;
    const size_t total = (size_t)BATCH * TT * DD;
    if (idx >= total) return;
    int d = (int)(idx % DD);
    size_t bt = idx / DD;
    int t = (int)(bt % TT);
    int b = (int)(bt / TT);
    float v;
    if (t < NX) v = x[((size_t)b * NX + t) * DD + d];
    else        v = mem[(size_t)d * MMEM + (t - NX)];   // mem[0, d, t-NX]
    g_XM[idx] = __float2half(v);
}

__global__ void cvt_w_half(const float* __restrict__ w) {
    size_t idx = (size_t)blockIdx.x * blockDim.x + threadIdx.x;
    if (idx < (size_t)D3 * DD) g_W[idx] = __float2half(w[idx]);
}

// ---------------------------------------------------------------------------
// Transpose V: VT[b][d][j] = QKV[b][j][2*DD + d]   (32x32 smem tiles)
// ---------------------------------------------------------------------------
__global__ void transpose_v(const __half* __restrict__ QKV, __half* __restrict__ VT) {
    __shared__ __half t[32][33];
    const int tx = threadIdx.x, ty = threadIdx.y;
    const int j0 = blockIdx.x * 32, d0 = blockIdx.y * 32, b = blockIdx.z;
    const __half* Vb = QKV + (size_t)b * TT * D3 + 2 * DD;
#pragma unroll
    for (int r = 0; r < 4; r++) {
        int j = j0 + ty + r * 8;
        t[ty + r * 8][tx] = Vb[(size_t)j * D3 + d0 + tx];
    }
    __syncthreads();
    __half* VTb = VT + (size_t)b * DD * TT;
#pragma unroll
    for (int r = 0; r < 4; r++) {
        int d = d0 + ty + r * 8;
        VTb[(size_t)d * TT + j0 + tx] = t[tx][ty + r * 8];
    }
}

// ---------------------------------------------------------------------------
// NT GEMM: C[m,n] = alpha * sum_k A[m*lda+k] * B[n*ldb+k]
// CTA 128x256, 8 warps (2m x 4n), warp tile 64x64, BK=32.
// 2-stage cp.async double buffer; both k-step fragment sets loaded up front
// (64 frag regs) so 64 independent MMAs hide the ldsm latency (ILP, not occ).
// smem [m][k]/[n][k] padded stride 40 halves (conflict-free, verified R3/R5).
// ---------------------------------------------------------------------------
#define NTS   40
#define STG_A (128 * NTS)      // halves per A stage
#define STG_B (256 * NTS)      // halves per B stage
#define GEMM_SMEM ((2 * STG_A + 2 * STG_B) * 2)   // 61440 bytes

template <typename CT>
__global__ __launch_bounds__(256, 1)
void gemm_nt_big(const __half* __restrict__ A, const __half* __restrict__ B,
                 CT* __restrict__ C, int Kdim,
                 int lda, int ldb, int ldc, float alpha,
                 size_t sA, size_t sB, size_t sC) {
    extern __shared__ __half sh[];
    __half* As = sh;                 // [2][STG_A]
    __half* Bs = sh + 2 * STG_A;     // [2][STG_B]
    A += (size_t)blockIdx.z * sA;
    B += (size_t)blockIdx.z * sB;
    C += (size_t)blockIdx.z * sC;
    const int m0 = blockIdx.y * 128;
    const int n0 = blockIdx.x * 256;
    const int tid  = threadIdx.x;
    const int lane = tid & 31;
    const int wid  = tid >> 5;
    const int mBase = (wid & 1) * 64;      // 2 m-warps
    const int nBase = (wid >> 1) * 64;     // 4 n-warps

    const uint32_t aSm = (uint32_t)__cvta_generic_to_shared(As);
    const uint32_t bSm = (uint32_t)__cvta_generic_to_shared(Bs);

    // global->smem mapping: chunk idx = tid + c*256; row = idx>>2, kcol = (idx&3)*8
    const int row4 = tid >> 2;             // 0..63
    const int kc   = (tid & 3) * 8;        // halves: 0,8,16,24
    const __half* Ag = A + (size_t)(m0 + row4) * lda + kc;
    const __half* Bg = B + (size_t)(n0 + row4) * ldb + kc;
    const uint32_t aSt = aSm + (uint32_t)(row4 * NTS + kc) * 2;
    const uint32_t bSt = bSm + (uint32_t)(row4 * NTS + kc) * 2;

    // ldmatrix lane bases (bytes): row = base+(lane&15), k-col = 8*(lane>>4)
    const uint32_t aFrag = aSm + ((mBase + (lane & 15)) * NTS + 8 * (lane >> 4)) * 2;
    const uint32_t bFrag = bSm + ((nBase + (lane & 15)) * NTS + 8 * (lane >> 4)) * 2;

    float acc[4][8][4] = {};

    // prologue: stage 0 (A: 2 chunks of 64 rows; B: 4 chunks of 64 rows)
#pragma unroll
    for (int c = 0; c < 2; c++)
        cpasync16(aSt + c * 64 * NTS * 2, Ag + (size_t)c * 64 * lda);
#pragma unroll
    for (int c = 0; c < 4; c++)
        cpasync16(bSt + c * 64 * NTS * 2, Bg + (size_t)c * 64 * ldb);
    cp_commit();

    const int nIter = Kdim >> 5;
    for (int t = 0; t < nIter; t++) {
        cp_wait0();
        __syncthreads();          // stage t ready; all warps done reading t-1
        if (t + 1 < nIter) {
            const int st = (t + 1) & 1;
            const int k0 = (t + 1) * 32;
            const uint32_t ao = aSt + st * STG_A * 2;
            const uint32_t bo = bSt + st * STG_B * 2;
#pragma unroll
            for (int c = 0; c < 2; c++)
                cpasync16(ao + c * 64 * NTS * 2, Ag + (size_t)c * 64 * lda + k0);
#pragma unroll
            for (int c = 0; c < 4; c++)
                cpasync16(bo + c * 64 * NTS * 2, Bg + (size_t)c * 64 * ldb + k0);
            cp_commit();
        }
        const uint32_t aO = aFrag + (t & 1) * STG_A * 2;
        const uint32_t bO = bFrag + (t & 1) * STG_B * 2;

        // load ALL fragments for both k16 steps first (16 independent ldsm),
        // then 64 independent MMAs — deep ILP to cover ldsm latency.
        uint32_t af[2][4][4], bf[2][4][4];
#pragma unroll
        for (int s = 0; s < 2; s++) {
#pragma unroll
            for (int mi = 0; mi < 4; mi++)
                ldsm4(af[s][mi], aO + (mi * 16 * NTS + s * 16) * 2);
#pragma unroll
            for (int u = 0; u < 4; u++)
                ldsm4(bf[s][u], bO + (u * 16 * NTS + s * 16) * 2);
        }
#pragma unroll
        for (int s = 0; s < 2; s++)
#pragma unroll
            for (int mi = 0; mi < 4; mi++)
#pragma unroll
                for (int ni = 0; ni < 8; ni++) {
                    // x4 regs: r0=(n+0,k0) r1=(n+8,k0) r2=(n+0,k8) r3=(n+8,k8)
                    uint32_t bb[2] = { bf[s][ni >> 1][ni & 1],
                                       bf[s][ni >> 1][(ni & 1) + 2] };
                    mma_f16(acc[s & 0 ? 0 : mi][ni], af[s][mi], bb);   // acc[mi][ni]
                }
    }

    const int g = lane >> 2, tg = lane & 3;
#pragma unroll
    for (int mi = 0; mi < 4; mi++) {
        int r0 = m0 + mBase + mi * 16 + g;
#pragma unroll
        for (int ni = 0; ni < 8; ni++) {
            int cb = n0 + nBase + ni * 8 + 2 * tg;
            if constexpr (sizeof(CT) == 2) {
                __half2 v0 = __floats2half2_rn(alpha * acc[mi][ni][0], alpha * acc[mi][ni][1]);
                __half2 v1 = __floats2half2_rn(alpha * acc[mi][ni][2], alpha * acc[mi][ni][3]);
                *reinterpret_cast<__half2*>((__half*)C + (size_t)r0 * ldc + cb) = v0;
                *reinterpret_cast<__half2*>((__half*)C + (size_t)(r0 + 8) * ldc + cb) = v1;
            } else {
                float2 v0 = make_float2(alpha * acc[mi][ni][0], alpha * acc[mi][ni][1]);
                float2 v1 = make_float2(alpha * acc[mi][ni][2], alpha * acc[mi][ni][3]);
                *reinterpret_cast<float2*>((float*)C + (size_t)r0 * ldc + cb) = v0;
                *reinterpret_cast<float2*>((float*)C + (size_t)(r0 + 8) * ldc + cb) = v1;
            }
        }
    }
}

// ---------------------------------------------------------------------------
// Column softmax of S'[i,j] over i (2 passes), scale folded, write fp16 P'.
// Block 512 = 128 cols x 4 row-groups; grid (TT/128, BATCH). Coalesced in j.
// ---------------------------------------------------------------------------
__global__ __launch_bounds__(512)
void col_softmax(const float* __restrict__ S, __half* __restrict__ P) {
    const int tid = threadIdx.x;
    const int c = tid & 127, r = tid >> 7;
    const int j = blockIdx.x * 128 + c;
    const int b = blockIdx.y;
    const float scale = 0.044194173824159216f;  // 1/sqrt(512)
    const float* Sb = S + (size_t)b * TT * TT;
    __half* Pb = P + (size_t)b * TT * TT;

    float m = -1e30f, z = 0.f;
    for (int i = r; i < TT; i += 4) {
        float v = Sb[(size_t)i * TT + j] * scale;
        float nm = fmaxf(m, v);
        z = z * __expf(m - nm) + __expf(v - nm);
        m = nm;
    }
    __shared__ float sm[4][128], sz[4][128];
    sm[r][c] = m; sz[r][c] = z;
    __syncthreads();
    float M = fmaxf(fmaxf(sm[0][c], sm[1][c]), fmaxf(sm[2][c], sm[3][c]));
    float Z = sz[0][c] * __expf(sm[0][c] - M) + sz[1][c] * __expf(sm[1][c] - M)
            + sz[2][c] * __expf(sm[2][c] - M) + sz[3][c] * __expf(sm[3][c] - M);
    float inv = 1.0f / Z;
    for (int i = r; i < TT; i += 4) {
        float v = Sb[(size_t)i * TT + j] * scale;
        Pb[(size_t)i * TT + j] = __float2half(__expf(v - M) * inv);
    }
}

// ---------------------------------------------------------------------------
// Launch: prep -> QKV -> S'[i,j]=K_i.Q_j -> col softmax -> VT -> out = P' VT^T
// ---------------------------------------------------------------------------
extern "C" void kernel_launch(void* const* d_in, const int* in_sizes, int n_in,
                              void* d_out, int out_size) {
    (void)in_sizes; (void)n_in; (void)out_size;
    const float* x   = (const float*)d_in[0];
    const float* mem = (const float*)d_in[1];
    const float* w   = (const float*)d_in[2];
    float* out = (float*)d_out;

    __half *XM = nullptr, *W = nullptr, *QKV = nullptr, *P = nullptr, *VT = nullptr;
    float *S = nullptr;
    cudaGetSymbolAddress((void**)&XM,  g_XM);
    cudaGetSymbolAddress((void**)&W,   g_W);
    cudaGetSymbolAddress((void**)&QKV, g_QKV);
    cudaGetSymbolAddress((void**)&S,   g_S);
    cudaGetSymbolAddress((void**)&P,   g_P);
    cudaGetSymbolAddress((void**)&VT,  g_VT);

    // 61440B dynamic smem > 48KB default: raise the per-kernel cap (host-side
    // attribute set; graph-capture-safe, idempotent)
    cudaFuncSetAttribute(gemm_nt_big<__half>,
                         cudaFuncAttributeMaxDynamicSharedMemorySize, GEMM_SMEM);
    cudaFuncSetAttribute(gemm_nt_big<float>,
                         cudaFuncAttributeMaxDynamicSharedMemorySize, GEMM_SMEM);

    // 1) prep fp16 inputs
    {
        size_t total = (size_t)BATCH * TT * DD;
        build_xm_half<<<(unsigned)((total + 255) / 256), 256>>>(x, mem);
        size_t wtot = (size_t)D3 * DD;
        cvt_w_half<<<(unsigned)((wtot + 255) / 256), 256>>>(w);
    }
    // 2) QKV = XM @ W^T   (M=18432, N=1536, K=512), fp16 out
    {
        dim3 grid(D3 / 256, (BATCH * TT) / 128, 1);
        gemm_nt_big<__half><<<grid, 256, GEMM_SMEM>>>(XM, W, QKV, DD,
                                                      DD, DD, D3, 1.0f, 0, 0, 0);
    }
    // 3) S'[i,j] = K_i . Q_j  (A = K rows, B = Q rows), fp32 out
    {
        dim3 grid(TT / 256, TT / 128, BATCH);
        gemm_nt_big<float><<<grid, 256, GEMM_SMEM>>>(QKV + DD, QKV, S, DD,
                                                     D3, D3, TT, 1.0f,
                                                     (size_t)TT * D3, (size_t)TT * D3,
                                                     (size_t)TT * TT);
    }
    // 4) column softmax over i (scale folded): P'[i,j] fp16
    {
        dim3 grid(TT / 128, BATCH, 1);
        col_softmax<<<grid, 512>>>(S, P);
    }
    // 5) VT[b][d][j] = V[b][j][d]
    {
        dim3 grid(TT / 32, DD / 32, BATCH);
        transpose_v<<<grid, dim3(32, 8, 1)>>>(QKV, VT);
    }
    // 6) out[b,i,d] = sum_j P'[i,j] * VT[d,j]   (NT; M=2304, N=512, K=2304)
    {
        dim3 grid(DD / 256, TT / 128, BATCH);
        gemm_nt_big<float><<<grid, 256, GEMM_SMEM>>>(P, VT, out, TT,
                                                     TT, TT, DD, 1.0f,
                                                     (size_t)TT * TT, (size_t)DD * TT,
                                                     (size_t)TT * DD);
    }
}

// round 9
// speedup vs baseline: 1.0841x; 1.0519x over previous
#include <cuda_runtime.h>
#include <cuda_fp16.h>
#include <math.h>
#include <stdint.h>

// Problem shape constants
#define BATCH 8
#define NX    2048
#define MMEM  256
#define TT    2304          // NX + MMEM
#define DD    512
#define D3    1536          // 3*DD

// Scratch (allocation-free: __device__ globals, 128B-aligned)
__device__ __align__(128) __half g_XM [(size_t)BATCH * TT * DD];   // 18.9 MB
__device__ __align__(128) __half g_W  [(size_t)D3 * DD];           //  1.5 MB
__device__ __align__(128) __half g_QKV[(size_t)BATCH * TT * D3];   // 56.6 MB
__device__ __align__(128) float  g_S  [(size_t)BATCH * TT * TT];   // 169.9 MB  S'[i,j]
__device__ __align__(128) __half g_P  [(size_t)BATCH * TT * TT];   // 85.0 MB   P'[i,j]
__device__ __align__(128) __half g_VT [(size_t)BATCH * DD * TT];   // 18.9 MB   V^T

// ---------------------------------------------------------------------------
// PTX helpers (sm_100 base ISA: mma.sync / ldmatrix / cp.async)
// ---------------------------------------------------------------------------
__device__ __forceinline__ void mma_f16(float* c, const uint32_t* a, const uint32_t* b) {
    asm volatile(
        "mma.sync.aligned.m16n8k16.row.col.f32.f16.f16.f32 "
        "{%0,%1,%2,%3}, {%4,%5,%6,%7}, {%8,%9}, {%0,%1,%2,%3};\n"
        : "+f"(c[0]), "+f"(c[1]), "+f"(c[2]), "+f"(c[3])
        : "r"(a[0]), "r"(a[1]), "r"(a[2]), "r"(a[3]), "r"(b[0]), "r"(b[1]));
}

__device__ __forceinline__ void ldsm4(uint32_t* r, uint32_t addr) {
    asm volatile("ldmatrix.sync.aligned.m8n8.x4.shared.b16 {%0,%1,%2,%3}, [%4];"
                 : "=r"(r[0]), "=r"(r[1]), "=r"(r[2]), "=r"(r[3]) : "r"(addr));
}

__device__ __forceinline__ void cpasync16(uint32_t s, const void* g) {
    asm volatile("cp.async.cg.shared.global [%0], [%1], 16;\n" :: "r"(s), "l"(g));
}
__device__ __forceinline__ void cp_commit() {
    asm volatile("cp.async.commit_group;\n" ::: "memory");
}
__device__ __forceinline__ void cp_wait0() {
    asm volatile("cp.async.wait_group 0;\n" ::: "memory");
}

// ---------------------------------------------------------------------------
// Input prep: XM = concat(x, mem^T) in fp16;  W -> fp16
// ---------------------------------------------------------------------------
__global__ void build_xm_half(const float* __restrict__ x,
                              const float* __restrict__ mem) {
    size_t idx = (size_t)blockIdx.x * blockDim.x + threadIdx.x;
    const size_t total = (size_t)BATCH * TT * DD;
    if (idx >= total) return;
    int d = (int)(idx % DD);
    size_t bt = idx / DD;
    int t = (int)(bt % TT);
    int b = (int)(bt / TT);
    float v;
    if (t < NX) v = x[((size_t)b * NX + t) * DD + d];
    else        v = mem[(size_t)d * MMEM + (t - NX)];   // mem[0, d, t-NX]
    g_XM[idx] = __float2half(v);
}

__global__ void cvt_w_half(const float* __restrict__ w) {
    size_t idx = (size_t)blockIdx.x * blockDim.x + threadIdx.x;
    if (idx < (size_t)D3 * DD) g_W[idx] = __float2half(w[idx]);
}

// ---------------------------------------------------------------------------
// Transpose V: VT[b][d][j] = QKV[b][j][2*DD + d]   (32x32 smem tiles)
// ---------------------------------------------------------------------------
__global__ void transpose_v(const __half* __restrict__ QKV, __half* __restrict__ VT) {
    __shared__ __half t[32][33];
    const int tx = threadIdx.x, ty = threadIdx.y;
    const int j0 = blockIdx.x * 32, d0 = blockIdx.y * 32, b = blockIdx.z;
    const __half* Vb = QKV + (size_t)b * TT * D3 + 2 * DD;
#pragma unroll
    for (int r = 0; r < 4; r++) {
        int j = j0 + ty + r * 8;
        t[ty + r * 8][tx] = Vb[(size_t)j * D3 + d0 + tx];
    }
    __syncthreads();
    __half* VTb = VT + (size_t)b * DD * TT;
#pragma unroll
    for (int r = 0; r < 4; r++) {
        int d = d0 + ty + r * 8;
        VTb[(size_t)d * TT + j0 + tx] = t[tx][ty + r * 8];
    }
}

// ---------------------------------------------------------------------------
// NT GEMM: C[m,n] = alpha * sum_k A[m*lda+k] * B[n*ldb+k]
// CTA 128x256, 8 warps (2m x 4n), warp tile 64x64, BK=64 (4 k16-steps).
// 2-stage cp.async smem pipeline + 2-deep register fragment pipeline:
// ldsm(step s+1) interleaved with mma(step s) so the tensor pipe never
// drains during fragment loads. smem stride 72 halves (conflict-free).
// ---------------------------------------------------------------------------
#define NTS   72
#define STG_A (128 * NTS)      // halves per A stage (18 KB)
#define STG_B (256 * NTS)      // halves per B stage (36 KB)
#define GEMM_SMEM ((2 * STG_A + 2 * STG_B) * 2)   // 110592 bytes

template <typename CT>
__global__ __launch_bounds__(256, 1)
void gemm_nt_big(const __half* __restrict__ A, const __half* __restrict__ B,
                 CT* __restrict__ C, int Kdim,
                 int lda, int ldb, int ldc, float alpha,
                 size_t sA, size_t sB, size_t sC) {
    extern __shared__ __half sh[];
    __half* As = sh;                 // [2][STG_A]
    __half* Bs = sh + 2 * STG_A;     // [2][STG_B]
    A += (size_t)blockIdx.z * sA;
    B += (size_t)blockIdx.z * sB;
    C += (size_t)blockIdx.z * sC;
    const int m0 = blockIdx.y * 128;
    const int n0 = blockIdx.x * 256;
    const int tid  = threadIdx.x;
    const int lane = tid & 31;
    const int wid  = tid >> 5;
    const int mBase = (wid & 1) * 64;      // 2 m-warps
    const int nBase = (wid >> 1) * 64;     // 4 n-warps

    const uint32_t aSm = (uint32_t)__cvta_generic_to_shared(As);
    const uint32_t bSm = (uint32_t)__cvta_generic_to_shared(Bs);

    // global->smem mapping: chunk idx; row = idx>>3, k8 = (idx&7)*8 halves
    const int rowA = tid >> 3;             // 0..31 (+32 per c)
    const int k8   = (tid & 7) * 8;        // 0..56
    const __half* Ag = A + (size_t)(m0 + rowA) * lda + k8;
    const __half* Bg = B + (size_t)(n0 + rowA) * ldb + k8;
    const uint32_t aSt = aSm + (uint32_t)(rowA * NTS + k8) * 2;
    const uint32_t bSt = bSm + (uint32_t)(rowA * NTS + k8) * 2;
    const uint32_t rowStep = 32 * NTS * 2;         // 32 rows in bytes

    // ldmatrix lane bases (bytes): row = base+(lane&15), k-col = 8*(lane>>4)
    const uint32_t aFrag = aSm + ((mBase + (lane & 15)) * NTS + 8 * (lane >> 4)) * 2;
    const uint32_t bFrag = bSm + ((nBase + (lane & 15)) * NTS + 8 * (lane >> 4)) * 2;

    float acc[4][8][4] = {};

    // prologue: stage 0 (A: 4 row-chunks of 32; B: 8 row-chunks of 32)
#pragma unroll
    for (int c = 0; c < 4; c++)
        cpasync16(aSt + c * rowStep, Ag + (size_t)c * 32 * lda);
#pragma unroll
    for (int c = 0; c < 8; c++)
        cpasync16(bSt + c * rowStep, Bg + (size_t)c * 32 * ldb);
    cp_commit();

    uint32_t af[2][4][4], bf[2][4][4];     // 2-deep fragment pipeline

    const int nIter = Kdim >> 6;
    for (int t = 0; t < nIter; t++) {
        cp_wait0();
        __syncthreads();          // stage t resident; all warps done with t-1
        if (t + 1 < nIter) {
            const int k0 = (t + 1) * 64;
            const uint32_t ao = aSt + ((t + 1) & 1) * STG_A * 2;
            const uint32_t bo = bSt + ((t + 1) & 1) * STG_B * 2;
#pragma unroll
            for (int c = 0; c < 4; c++)
                cpasync16(ao + c * rowStep, Ag + (size_t)c * 32 * lda + k0);
#pragma unroll
            for (int c = 0; c < 8; c++)
                cpasync16(bo + c * rowStep, Bg + (size_t)c * 32 * ldb + k0);
            cp_commit();
        }
        const uint32_t aO = aFrag + (t & 1) * STG_A * 2;
        const uint32_t bO = bFrag + (t & 1) * STG_B * 2;

        // fragment pipeline: load step 0, then overlap ldsm(s+1) with mma(s)
#pragma unroll
        for (int mi = 0; mi < 4; mi++) ldsm4(af[0][mi], aO + (mi * 16 * NTS) * 2);
#pragma unroll
        for (int u = 0; u < 4; u++)    ldsm4(bf[0][u],  bO + (u * 16 * NTS) * 2);
#pragma unroll
        for (int s = 0; s < 4; s++) {
            const int cur = s & 1, nxt = cur ^ 1;
            if (s < 3) {
#pragma unroll
                for (int mi = 0; mi < 4; mi++)
                    ldsm4(af[nxt][mi], aO + (mi * 16 * NTS + (s + 1) * 16) * 2);
#pragma unroll
                for (int u = 0; u < 4; u++)
                    ldsm4(bf[nxt][u],  bO + (u * 16 * NTS + (s + 1) * 16) * 2);
            }
#pragma unroll
            for (int mi = 0; mi < 4; mi++)
#pragma unroll
                for (int ni = 0; ni < 8; ni++) {
                    // x4 regs: r0=(n+0,k0) r1=(n+8,k0) r2=(n+0,k8) r3=(n+8,k8)
                    uint32_t bb[2] = { bf[cur][ni >> 1][ni & 1],
                                       bf[cur][ni >> 1][(ni & 1) + 2] };
                    mma_f16(acc[mi][ni], af[cur][mi], bb);
                }
        }
    }

    const int g = lane >> 2, tg = lane & 3;
#pragma unroll
    for (int mi = 0; mi < 4; mi++) {
        int r0 = m0 + mBase + mi * 16 + g;
#pragma unroll
        for (int ni = 0; ni < 8; ni++) {
            int cb = n0 + nBase + ni * 8 + 2 * tg;
            if constexpr (sizeof(CT) == 2) {
                __half2 v0 = __floats2half2_rn(alpha * acc[mi][ni][0], alpha * acc[mi][ni][1]);
                __half2 v1 = __floats2half2_rn(alpha * acc[mi][ni][2], alpha * acc[mi][ni][3]);
                *reinterpret_cast<__half2*>((__half*)C + (size_t)r0 * ldc + cb) = v0;
                *reinterpret_cast<__half2*>((__half*)C + (size_t)(r0 + 8) * ldc + cb) = v1;
            } else {
                float2 v0 = make_float2(alpha * acc[mi][ni][0], alpha * acc[mi][ni][1]);
                float2 v1 = make_float2(alpha * acc[mi][ni][2], alpha * acc[mi][ni][3]);
                *reinterpret_cast<float2*>((float*)C + (size_t)r0 * ldc + cb) = v0;
                *reinterpret_cast<float2*>((float*)C + (size_t)(r0 + 8) * ldc + cb) = v1;
            }
        }
    }
}

// ---------------------------------------------------------------------------
// Column softmax of S'[i,j] over i (2 passes), scale folded, write fp16 P'.
// Block 512 = 128 cols x 4 row-groups; grid (TT/128, BATCH). Coalesced in j.
// ---------------------------------------------------------------------------
__global__ __launch_bounds__(512)
void col_softmax(const float* __restrict__ S, __half* __restrict__ P) {
    const int tid = threadIdx.x;
    const int c = tid & 127, r = tid >> 7;
    const int j = blockIdx.x * 128 + c;
    const int b = blockIdx.y;
    const float scale = 0.044194173824159216f;  // 1/sqrt(512)
    const float* Sb = S + (size_t)b * TT * TT;
    __half* Pb = P + (size_t)b * TT * TT;

    float m = -1e30f, z = 0.f;
    for (int i = r; i < TT; i += 4) {
        float v = Sb[(size_t)i * TT + j] * scale;
        float nm = fmaxf(m, v);
        z = z * __expf(m - nm) + __expf(v - nm);
        m = nm;
    }
    __shared__ float sm[4][128], sz[4][128];
    sm[r][c] = m; sz[r][c] = z;
    __syncthreads();
    float M = fmaxf(fmaxf(sm[0][c], sm[1][c]), fmaxf(sm[2][c], sm[3][c]));
    float Z = sz[0][c] * __expf(sm[0][c] - M) + sz[1][c] * __expf(sm[1][c] - M)
            + sz[2][c] * __expf(sm[2][c] - M) + sz[3][c] * __expf(sm[3][c] - M);
    float inv = 1.0f / Z;
    for (int i = r; i < TT; i += 4) {
        float v = Sb[(size_t)i * TT + j] * scale;
        Pb[(size_t)i * TT + j] = __float2half(__expf(v - M) * inv);
    }
}

// ---------------------------------------------------------------------------
// Launch: prep -> QKV -> S'[i,j]=K_i.Q_j -> col softmax -> VT -> out = P' VT^T
// ---------------------------------------------------------------------------
extern "C" void kernel_launch(void* const* d_in, const int* in_sizes, int n_in,
                              void* d_out, int out_size) {
    (void)in_sizes; (void)n_in; (void)out_size;
    const float* x   = (const float*)d_in[0];
    const float* mem = (const float*)d_in[1];
    const float* w   = (const float*)d_in[2];
    float* out = (float*)d_out;

    __half *XM = nullptr, *W = nullptr, *QKV = nullptr, *P = nullptr, *VT = nullptr;
    float *S = nullptr;
    cudaGetSymbolAddress((void**)&XM,  g_XM);
    cudaGetSymbolAddress((void**)&W,   g_W);
    cudaGetSymbolAddress((void**)&QKV, g_QKV);
    cudaGetSymbolAddress((void**)&S,   g_S);
    cudaGetSymbolAddress((void**)&P,   g_P);
    cudaGetSymbolAddress((void**)&VT,  g_VT);

    cudaFuncSetAttribute(gemm_nt_big<__half>,
                         cudaFuncAttributeMaxDynamicSharedMemorySize, GEMM_SMEM);
    cudaFuncSetAttribute(gemm_nt_big<float>,
                         cudaFuncAttributeMaxDynamicSharedMemorySize, GEMM_SMEM);

    // 1) prep fp16 inputs
    {
        size_t total = (size_t)BATCH * TT * DD;
        build_xm_half<<<(unsigned)((total + 255) / 256), 256>>>(x, mem);
        size_t wtot = (size_t)D3 * DD;
        cvt_w_half<<<(unsigned)((wtot + 255) / 256), 256>>>(w);
    }
    // 2) QKV = XM @ W^T   (M=18432, N=1536, K=512), fp16 out
    {
        dim3 grid(D3 / 256, (BATCH * TT) / 128, 1);
        gemm_nt_big<__half><<<grid, 256, GEMM_SMEM>>>(XM, W, QKV, DD,
                                                      DD, DD, D3, 1.0f, 0, 0, 0);
    }
    // 3) S'[i,j] = K_i . Q_j  (A = K rows, B = Q rows), fp32 out
    {
        dim3 grid(TT / 256, TT / 128, BATCH);
        gemm_nt_big<float><<<grid, 256, GEMM_SMEM>>>(QKV + DD, QKV, S, DD,
                                                     D3, D3, TT, 1.0f,
                                                     (size_t)TT * D3, (size_t)TT * D3,
                                                     (size_t)TT * TT);
    }
    // 4) column softmax over i (scale folded): P'[i,j] fp16
    {
        dim3 grid(TT / 128, BATCH, 1);
        col_softmax<<<grid, 512>>>(S, P);
    }
    // 5) VT[b][d][j] = V[b][j][d]
    {
        dim3 grid(TT / 32, DD / 32, BATCH);
        transpose_v<<<grid, dim3(32, 8, 1)>>>(QKV, VT);
    }
    // 6) out[b,i,d] = sum_j P'[i,j] * VT[d,j]   (NT; M=2304, N=512, K=2304)
    {
        dim3 grid(DD / 256, TT / 128, BATCH);
        gemm_nt_big<float><<<grid, 256, GEMM_SMEM>>>(P, VT, out, TT,
                                                     TT, TT, DD, 1.0f,
                                                     (size_t)TT * TT, (size_t)DD * TT,
                                                     (size_t)TT * DD);
    }
}

// round 11
// speedup vs baseline: 1.3835x; 1.2761x over previous
#include <cuda_runtime.h>
#include <cuda_fp16.h>
#include <math.h>
#include <stdint.h>

// Problem shape constants
#define BATCH 8
#define NX    2048
#define MMEM  256
#define TT    2304          // NX + MMEM
#define DD    512
#define D3    1536          // 3*DD

// Scratch (allocation-free: __device__ globals, 128B-aligned)
__device__ __align__(128) __half g_XM [(size_t)BATCH * TT * DD];   // 18.9 MB
__device__ __align__(128) __half g_W  [(size_t)D3 * DD];           //  1.5 MB
__device__ __align__(128) __half g_QKV[(size_t)BATCH * TT * D3];   // 56.6 MB
__device__ __align__(128) float  g_S  [(size_t)BATCH * TT * TT];   // 169.9 MB  S[j,i]
__device__ __align__(128) __half g_P  [(size_t)BATCH * TT * TT];   // 85.0 MB   P[j,i]

// ---------------------------------------------------------------------------
// PTX helpers (sm_100 base ISA: mma.sync / ldmatrix / cp.async)
// ---------------------------------------------------------------------------
__device__ __forceinline__ void mma_f16(float* c, const uint32_t* a, const uint32_t* b) {
    asm volatile(
        "mma.sync.aligned.m16n8k16.row.col.f32.f16.f16.f32 "
        "{%0,%1,%2,%3}, {%4,%5,%6,%7}, {%8,%9}, {%0,%1,%2,%3};\n"
        : "+f"(c[0]), "+f"(c[1]), "+f"(c[2]), "+f"(c[3])
        : "r"(a[0]), "r"(a[1]), "r"(a[2]), "r"(a[3]), "r"(b[0]), "r"(b[1]));
}

__device__ __forceinline__ void ldsm4(uint32_t* r, uint32_t addr) {
    asm volatile("ldmatrix.sync.aligned.m8n8.x4.shared.b16 {%0,%1,%2,%3}, [%4];"
                 : "=r"(r[0]), "=r"(r[1]), "=r"(r[2]), "=r"(r[3]) : "r"(addr));
}

__device__ __forceinline__ void ldsm4t(uint32_t* r, uint32_t addr) {
    asm volatile("ldmatrix.sync.aligned.m8n8.x4.trans.shared.b16 {%0,%1,%2,%3}, [%4];"
                 : "=r"(r[0]), "=r"(r[1]), "=r"(r[2]), "=r"(r[3]) : "r"(addr));
}

__device__ __forceinline__ void cpasync16(uint32_t s, const void* g) {
    asm volatile("cp.async.cg.shared.global [%0], [%1], 16;\n" :: "r"(s), "l"(g));
}
__device__ __forceinline__ void cp_commit() {
    asm volatile("cp.async.commit_group;\n" ::: "memory");
}
__device__ __forceinline__ void cp_wait0() {
    asm volatile("cp.async.wait_group 0;\n" ::: "memory");
}

// ---------------------------------------------------------------------------
// Input prep: XM = concat(x, mem^T) in fp16;  W -> fp16
// ---------------------------------------------------------------------------
__global__ void build_xm_half(const float* __restrict__ x,
                              const float* __restrict__ mem) {
    size_t idx = (size_t)blockIdx.x * blockDim.x + threadIdx.x;
    const size_t total = (size_t)BATCH * TT * DD;
    if (idx >= total) return;
    int d = (int)(idx % DD);
    size_t bt = idx / DD;
    int t = (int)(bt % TT);
    int b = (int)(bt / TT);
    float v;
    if (t < NX) v = x[((size_t)b * NX + t) * DD + d];
    else        v = mem[(size_t)d * MMEM + (t - NX)];   // mem[0, d, t-NX]
    g_XM[idx] = __float2half(v);
}

__global__ void cvt_w_half(const float* __restrict__ w) {
    size_t idx = (size_t)blockIdx.x * blockDim.x + threadIdx.x;
    if (idx < (size_t)D3 * DD) g_W[idx] = __float2half(w[idx]);
}

// ---------------------------------------------------------------------------
// NT GEMM: C[m,n] = alpha * sum_k A[m*lda+k] * B[n*ldb+k]
// CTA 128x256, 8 warps (2m x 4n), warp tile 64x64, BK=64 (4 k16-steps).
// 2-stage cp.async smem pipeline + 2-deep register fragment pipeline.
// smem [m][k]/[n][k], stride 72 halves (conflict-free).       (round-9 core)
// ---------------------------------------------------------------------------
#define NTS   72
#define STG_A (128 * NTS)
#define STG_B (256 * NTS)
#define GEMM_SMEM ((2 * STG_A + 2 * STG_B) * 2)   // 110592 bytes

template <typename CT>
__global__ __launch_bounds__(256, 1)
void gemm_nt_big(const __half* __restrict__ A, const __half* __restrict__ B,
                 CT* __restrict__ C, int Kdim,
                 int lda, int ldb, int ldc, float alpha,
                 size_t sA, size_t sB, size_t sC) {
    extern __shared__ __half sh[];
    __half* As = sh;                 // [2][STG_A]
    __half* Bs = sh + 2 * STG_A;     // [2][STG_B]
    A += (size_t)blockIdx.z * sA;
    B += (size_t)blockIdx.z * sB;
    C += (size_t)blockIdx.z * sC;
    const int m0 = blockIdx.y * 128;
    const int n0 = blockIdx.x * 256;
    const int tid  = threadIdx.x;
    const int lane = tid & 31;
    const int wid  = tid >> 5;
    const int mBase = (wid & 1) * 64;
    const int nBase = (wid >> 1) * 64;

    const uint32_t aSm = (uint32_t)__cvta_generic_to_shared(As);
    const uint32_t bSm = (uint32_t)__cvta_generic_to_shared(Bs);

    const int rowA = tid >> 3;             // 0..31 (+32 per c)
    const int k8   = (tid & 7) * 8;        // 0..56
    const __half* Ag = A + (size_t)(m0 + rowA) * lda + k8;
    const __half* Bg = B + (size_t)(n0 + rowA) * ldb + k8;
    const uint32_t aSt = aSm + (uint32_t)(rowA * NTS + k8) * 2;
    const uint32_t bSt = bSm + (uint32_t)(rowA * NTS + k8) * 2;
    const uint32_t rowStep = 32 * NTS * 2;

    const uint32_t aFrag = aSm + ((mBase + (lane & 15)) * NTS + 8 * (lane >> 4)) * 2;
    const uint32_t bFrag = bSm + ((nBase + (lane & 15)) * NTS + 8 * (lane >> 4)) * 2;

    float acc[4][8][4] = {};

#pragma unroll
    for (int c = 0; c < 4; c++)
        cpasync16(aSt + c * rowStep, Ag + (size_t)c * 32 * lda);
#pragma unroll
    for (int c = 0; c < 8; c++)
        cpasync16(bSt + c * rowStep, Bg + (size_t)c * 32 * ldb);
    cp_commit();

    uint32_t af[2][4][4], bf[2][4][4];

    const int nIter = Kdim >> 6;
    for (int t = 0; t < nIter; t++) {
        cp_wait0();
        __syncthreads();
        if (t + 1 < nIter) {
            const int k0 = (t + 1) * 64;
            const uint32_t ao = aSt + ((t + 1) & 1) * STG_A * 2;
            const uint32_t bo = bSt + ((t + 1) & 1) * STG_B * 2;
#pragma unroll
            for (int c = 0; c < 4; c++)
                cpasync16(ao + c * rowStep, Ag + (size_t)c * 32 * lda + k0);
#pragma unroll
            for (int c = 0; c < 8; c++)
                cpasync16(bo + c * rowStep, Bg + (size_t)c * 32 * ldb + k0);
            cp_commit();
        }
        const uint32_t aO = aFrag + (t & 1) * STG_A * 2;
        const uint32_t bO = bFrag + (t & 1) * STG_B * 2;

#pragma unroll
        for (int mi = 0; mi < 4; mi++) ldsm4(af[0][mi], aO + (mi * 16 * NTS) * 2);
#pragma unroll
        for (int u = 0; u < 4; u++)    ldsm4(bf[0][u],  bO + (u * 16 * NTS) * 2);
#pragma unroll
        for (int s = 0; s < 4; s++) {
            const int cur = s & 1, nxt = cur ^ 1;
            if (s < 3) {
#pragma unroll
                for (int mi = 0; mi < 4; mi++)
                    ldsm4(af[nxt][mi], aO + (mi * 16 * NTS + (s + 1) * 16) * 2);
#pragma unroll
                for (int u = 0; u < 4; u++)
                    ldsm4(bf[nxt][u],  bO + (u * 16 * NTS + (s + 1) * 16) * 2);
            }
#pragma unroll
            for (int mi = 0; mi < 4; mi++)
#pragma unroll
                for (int ni = 0; ni < 8; ni++) {
                    // x4 regs: r0=(n+0,k0) r1=(n+8,k0) r2=(n+0,k8) r3=(n+8,k8)
                    uint32_t bb[2] = { bf[cur][ni >> 1][ni & 1],
                                       bf[cur][ni >> 1][(ni & 1) + 2] };
                    mma_f16(acc[mi][ni], af[cur][mi], bb);
                }
        }
    }

    const int g = lane >> 2, tg = lane & 3;
#pragma unroll
    for (int mi = 0; mi < 4; mi++) {
        int r0 = m0 + mBase + mi * 16 + g;
#pragma unroll
        for (int ni = 0; ni < 8; ni++) {
            int cb = n0 + nBase + ni * 8 + 2 * tg;
            if constexpr (sizeof(CT) == 2) {
                __half2 v0 = __floats2half2_rn(alpha * acc[mi][ni][0], alpha * acc[mi][ni][1]);
                __half2 v1 = __floats2half2_rn(alpha * acc[mi][ni][2], alpha * acc[mi][ni][3]);
                *reinterpret_cast<__half2*>((__half*)C + (size_t)r0 * ldc + cb) = v0;
                *reinterpret_cast<__half2*>((__half*)C + (size_t)(r0 + 8) * ldc + cb) = v1;
            } else {
                float2 v0 = make_float2(alpha * acc[mi][ni][0], alpha * acc[mi][ni][1]);
                float2 v1 = make_float2(alpha * acc[mi][ni][2], alpha * acc[mi][ni][3]);
                *reinterpret_cast<float2*>((float*)C + (size_t)r0 * ldc + cb) = v0;
                *reinterpret_cast<float2*>((float*)C + (size_t)(r0 + 8) * ldc + cb) = v1;
            }
        }
    }
}

// ---------------------------------------------------------------------------
// TN GEMM: C[m,n] = sum_k A[k*lda+m] * B[k*ldb+n], C fp32.
// CTA 128x256, 8 warps (2m x 4n), warp tile 64x64, BK=64 (4 k16-steps).
// smem [k][m] stride 136 / [k][n] stride 264; trans-ldmatrix (round-3 maps).
// Same 2-stage cp.async + 2-deep fragment pipeline as NT.
// ---------------------------------------------------------------------------
#define TNS_M 136
#define TNS_N 264
#define TSTG_A (64 * TNS_M)
#define TSTG_B (64 * TNS_N)
#define TGEMM_SMEM ((2 * TSTG_A + 2 * TSTG_B) * 2)   // 102400 bytes

__global__ __launch_bounds__(256, 1)
void gemm_tn_big(const __half* __restrict__ A, const __half* __restrict__ B,
                 float* __restrict__ C, int Kdim,
                 int lda, int ldb, int ldc,
                 size_t sA, size_t sB, size_t sC) {
    extern __shared__ __half sh[];
    __half* As = sh;                  // [2][TSTG_A]
    __half* Bs = sh + 2 * TSTG_A;     // [2][TSTG_B]
    A += (size_t)blockIdx.z * sA;
    B += (size_t)blockIdx.z * sB;
    C += (size_t)blockIdx.z * sC;
    const int m0 = blockIdx.y * 128;
    const int n0 = blockIdx.x * 256;
    const int tid  = threadIdx.x;
    const int lane = tid & 31;
    const int wid  = tid >> 5;
    const int mBase = (wid & 1) * 64;
    const int nBase = (wid >> 1) * 64;

    const uint32_t aSm = (uint32_t)__cvta_generic_to_shared(As);
    const uint32_t bSm = (uint32_t)__cvta_generic_to_shared(Bs);

    // global->smem: A 64k x 128m (16 chunks/row, 4/thread); B 64k x 256n (32, 8/thread)
    const int arow = tid >> 4;             // 0..15 (+16 per c)
    const int acol = (tid & 15) * 8;       // halves 0..120
    const int brow = tid >> 5;             // 0..7 (+8 per c)
    const int bcol = (tid & 31) * 8;       // halves 0..248
    const __half* Ag = A + (size_t)arow * lda + m0 + acol;
    const __half* Bg = B + (size_t)brow * ldb + n0 + bcol;
    const uint32_t aSt = aSm + (uint32_t)(arow * TNS_M + acol) * 2;
    const uint32_t bSt = bSm + (uint32_t)(brow * TNS_N + bcol) * 2;

    // trans-ldmatrix lane bases (round-3 verified mappings)
    // A frags: (k0,m0),(k0,m8),(k8,m0),(k8,m8)
    const uint32_t aFrag = aSm +
        (((lane & 7) + 8 * (lane >> 4)) * TNS_M + mBase + 8 * ((lane >> 3) & 1)) * 2;
    // B frags: (k0,n0),(k8,n0),(k0,n8),(k8,n8)
    const uint32_t bFrag = bSm +
        (((lane & 7) + 8 * ((lane >> 3) & 1)) * TNS_N + nBase + 8 * (lane >> 4)) * 2;

    float acc[4][8][4] = {};

#pragma unroll
    for (int c = 0; c < 4; c++)
        cpasync16(aSt + c * 16 * TNS_M * 2, Ag + (size_t)c * 16 * lda);
#pragma unroll
    for (int c = 0; c < 8; c++)
        cpasync16(bSt + c * 8 * TNS_N * 2, Bg + (size_t)c * 8 * ldb);
    cp_commit();

    uint32_t af[2][4][4], bf[2][4][4];

    const int nIter = Kdim >> 6;
    for (int t = 0; t < nIter; t++) {
        cp_wait0();
        __syncthreads();
        if (t + 1 < nIter) {
            const size_t k0 = (size_t)(t + 1) * 64;
            const uint32_t ao = aSt + ((t + 1) & 1) * TSTG_A * 2;
            const uint32_t bo = bSt + ((t + 1) & 1) * TSTG_B * 2;
#pragma unroll
            for (int c = 0; c < 4; c++)
                cpasync16(ao + c * 16 * TNS_M * 2, Ag + (k0 + c * 16) * lda);
#pragma unroll
            for (int c = 0; c < 8; c++)
                cpasync16(bo + c * 8 * TNS_N * 2, Bg + (k0 + c * 8) * ldb);
            cp_commit();
        }
        const uint32_t aO = aFrag + (t & 1) * TSTG_A * 2;
        const uint32_t bO = bFrag + (t & 1) * TSTG_B * 2;

#pragma unroll
        for (int mi = 0; mi < 4; mi++) ldsm4t(af[0][mi], aO + (mi * 16) * 2);
#pragma unroll
        for (int u = 0; u < 4; u++)    ldsm4t(bf[0][u],  bO + (u * 16) * 2);
#pragma unroll
        for (int s = 0; s < 4; s++) {
            const int cur = s & 1, nxt = cur ^ 1;
            if (s < 3) {
#pragma unroll
                for (int mi = 0; mi < 4; mi++)
                    ldsm4t(af[nxt][mi], aO + ((s + 1) * 16 * TNS_M + mi * 16) * 2);
#pragma unroll
                for (int u = 0; u < 4; u++)
                    ldsm4t(bf[nxt][u],  bO + ((s + 1) * 16 * TNS_N + u * 16) * 2);
            }
#pragma unroll
            for (int mi = 0; mi < 4; mi++)
#pragma unroll
                for (int ni = 0; ni < 8; ni++) {
                    // x4 regs: r0=(k0,n+0) r1=(k8,n+0) r2=(k0,n+8) r3=(k8,n+8)
                    uint32_t bb[2] = { bf[cur][ni >> 1][2 * (ni & 1)],
                                       bf[cur][ni >> 1][2 * (ni & 1) + 1] };
                    mma_f16(acc[mi][ni], af[cur][mi], bb);
                }
        }
    }

    const int g = lane >> 2, tg = lane & 3;
#pragma unroll
    for (int mi = 0; mi < 4; mi++) {
        int r0 = m0 + mBase + mi * 16 + g;
#pragma unroll
        for (int ni = 0; ni < 8; ni++) {
            int cb = n0 + nBase + ni * 8 + 2 * tg;
            float2 v0 = make_float2(acc[mi][ni][0], acc[mi][ni][1]);
            float2 v1 = make_float2(acc[mi][ni][2], acc[mi][ni][3]);
            *reinterpret_cast<float2*>(C + (size_t)r0 * ldc + cb) = v0;
            *reinterpret_cast<float2*>(C + (size_t)(r0 + 8) * ldc + cb) = v1;
        }
    }
}

// ---------------------------------------------------------------------------
// Row softmax over T=2304 columns: read fp32 logits, write fp16 probs.
// ---------------------------------------------------------------------------
__global__ __launch_bounds__(256)
void softmax_rows_kernel(const float* __restrict__ S, __half* __restrict__ P) {
    const float* row = S + (size_t)blockIdx.x * TT;
    __half* prow = P + (size_t)blockIdx.x * TT;
    const int tid = threadIdx.x;
    __shared__ float red[8];

    float v[9];
    float lmax = -1e30f;
#pragma unroll
    for (int it = 0; it < 9; it++) {
        v[it] = row[tid + it * 256];
        lmax = fmaxf(lmax, v[it]);
    }
#pragma unroll
    for (int o = 16; o; o >>= 1)
        lmax = fmaxf(lmax, __shfl_xor_sync(0xffffffffu, lmax, o));
    if ((tid & 31) == 0) red[tid >> 5] = lmax;
    __syncthreads();
    float m = red[0];
#pragma unroll
    for (int w = 1; w < 8; w++) m = fmaxf(m, red[w]);

    float e[9];
    float lsum = 0.f;
#pragma unroll
    for (int it = 0; it < 9; it++) {
        e[it] = __expf(v[it] - m);
        lsum += e[it];
    }
#pragma unroll
    for (int o = 16; o; o >>= 1)
        lsum += __shfl_xor_sync(0xffffffffu, lsum, o);
    __syncthreads();
    if ((tid & 31) == 0) red[tid >> 5] = lsum;
    __syncthreads();
    float Z = 0.f;
#pragma unroll
    for (int w = 0; w < 8; w++) Z += red[w];
    float inv = 1.0f / Z;
#pragma unroll
    for (int it = 0; it < 9; it++)
        prow[tid + it * 256] = __float2half(e[it] * inv);
}

// ---------------------------------------------------------------------------
// Launch: prep -> QKV -> S[j,i]=Q_j.K_i/sqrt(D) -> row softmax -> out = P^T V
// ---------------------------------------------------------------------------
extern "C" void kernel_launch(void* const* d_in, const int* in_sizes, int n_in,
                              void* d_out, int out_size) {
    (void)in_sizes; (void)n_in; (void)out_size;
    const float* x   = (const float*)d_in[0];
    const float* mem = (const float*)d_in[1];
    const float* w   = (const float*)d_in[2];
    float* out = (float*)d_out;

    __half *XM = nullptr, *W = nullptr, *QKV = nullptr, *P = nullptr;
    float *S = nullptr;
    cudaGetSymbolAddress((void**)&XM,  g_XM);
    cudaGetSymbolAddress((void**)&W,   g_W);
    cudaGetSymbolAddress((void**)&QKV, g_QKV);
    cudaGetSymbolAddress((void**)&S,   g_S);
    cudaGetSymbolAddress((void**)&P,   g_P);

    cudaFuncSetAttribute(gemm_nt_big<__half>,
                         cudaFuncAttributeMaxDynamicSharedMemorySize, GEMM_SMEM);
    cudaFuncSetAttribute(gemm_nt_big<float>,
                         cudaFuncAttributeMaxDynamicSharedMemorySize, GEMM_SMEM);
    cudaFuncSetAttribute(gemm_tn_big,
                         cudaFuncAttributeMaxDynamicSharedMemorySize, TGEMM_SMEM);

    // 1) prep fp16 inputs
    {
        size_t total = (size_t)BATCH * TT * DD;
        build_xm_half<<<(unsigned)((total + 255) / 256), 256>>>(x, mem);
        size_t wtot = (size_t)D3 * DD;
        cvt_w_half<<<(unsigned)((wtot + 255) / 256), 256>>>(w);
    }
    // 2) QKV = XM @ W^T   (M=18432, N=1536, K=512), fp16 out
    {
        dim3 grid(D3 / 256, (BATCH * TT) / 128, 1);
        gemm_nt_big<__half><<<grid, 256, GEMM_SMEM>>>(XM, W, QKV, DD,
                                                      DD, DD, D3, 1.0f, 0, 0, 0);
    }
    // 3) S[j,i] = Q_j . K_i / sqrt(D)  (A=Q rows, B=K rows), fp32 out
    {
        dim3 grid(TT / 256, TT / 128, BATCH);
        const float scale = 0.044194173824159216f;  // 1/sqrt(512)
        gemm_nt_big<float><<<grid, 256, GEMM_SMEM>>>(QKV, QKV + DD, S, DD,
                                                     D3, D3, TT, scale,
                                                     (size_t)TT * D3, (size_t)TT * D3,
                                                     (size_t)TT * TT);
    }
    // 4) row softmax: fp32 S -> fp16 P
    softmax_rows_kernel<<<BATCH * TT, 256>>>(S, P);
    // 5) out[i,d] = sum_j P[j,i] * V[j,d]   (TN; M=2304, N=512, K=2304)
    {
        dim3 grid(DD / 256, TT / 128, BATCH);
        gemm_tn_big<<<grid, 256, TGEMM_SMEM>>>(P, QKV + 2 * DD, out, TT,
                                               TT, D3, DD,
                                               (size_t)TT * TT, (size_t)TT * D3,
                                               (size_t)TT * DD);
    }
}

// round 13
// speedup vs baseline: 1.4395x; 1.0405x over previous
#include <cuda_runtime.h>
#include <cuda_fp16.h>
#include <math.h>
#include <stdint.h>

// Problem shape constants
#define BATCH 8
#define NX    2048
#define MMEM  256
#define TT    2304          // NX + MMEM
#define DD    512
#define D3    1536          // 3*DD

// Scratch (allocation-free: __device__ globals, 128B-aligned)
__device__ __align__(128) __half g_XM [(size_t)BATCH * TT * DD];   // 18.9 MB
__device__ __align__(128) __half g_W  [(size_t)D3 * DD];           //  1.5 MB
__device__ __align__(128) __half g_QKV[(size_t)BATCH * TT * D3];   // 56.6 MB
__device__ __align__(128) float  g_S  [(size_t)BATCH * TT * TT];   // 169.9 MB  S[j,i]
__device__ __align__(128) __half g_P  [(size_t)BATCH * TT * TT];   // 85.0 MB   P[j,i]

// ---------------------------------------------------------------------------
// PTX helpers (sm_100 base ISA: mma.sync / ldmatrix / cp.async)
// ---------------------------------------------------------------------------
__device__ __forceinline__ void mma_f16(float* c, const uint32_t* a, const uint32_t* b) {
    asm volatile(
        "mma.sync.aligned.m16n8k16.row.col.f32.f16.f16.f32 "
        "{%0,%1,%2,%3}, {%4,%5,%6,%7}, {%8,%9}, {%0,%1,%2,%3};\n"
        : "+f"(c[0]), "+f"(c[1]), "+f"(c[2]), "+f"(c[3])
        : "r"(a[0]), "r"(a[1]), "r"(a[2]), "r"(a[3]), "r"(b[0]), "r"(b[1]));
}

__device__ __forceinline__ void ldsm4(uint32_t* r, uint32_t addr) {
    asm volatile("ldmatrix.sync.aligned.m8n8.x4.shared.b16 {%0,%1,%2,%3}, [%4];"
                 : "=r"(r[0]), "=r"(r[1]), "=r"(r[2]), "=r"(r[3]) : "r"(addr));
}

__device__ __forceinline__ void ldsm4t(uint32_t* r, uint32_t addr) {
    asm volatile("ldmatrix.sync.aligned.m8n8.x4.trans.shared.b16 {%0,%1,%2,%3}, [%4];"
                 : "=r"(r[0]), "=r"(r[1]), "=r"(r[2]), "=r"(r[3]) : "r"(addr));
}

__device__ __forceinline__ void cpasync16(uint32_t s, const void* g) {
    asm volatile("cp.async.cg.shared.global [%0], [%1], 16;\n" :: "r"(s), "l"(g));
}
__device__ __forceinline__ void cp_commit() {
    asm volatile("cp.async.commit_group;\n" ::: "memory");
}
__device__ __forceinline__ void cp_wait0() {
    asm volatile("cp.async.wait_group 0;\n" ::: "memory");
}

// ---------------------------------------------------------------------------
// Input prep: XM = concat(x, mem^T) in fp16;  W -> fp16
// ---------------------------------------------------------------------------
__global__ void build_xm_half(const float* __restrict__ x,
                              const float* __restrict__ mem) {
    size_t idx = (size_t)blockIdx.x * blockDim.x + threadIdx.x;
    const size_t total = (size_t)BATCH * TT * DD;
    if (idx >= total) return;
    int d = (int)(idx % DD);
    size_t bt = idx / DD;
    int t = (int)(bt % TT);
    int b = (int)(bt / TT);
    float v;
    if (t < NX) v = x[((size_t)b * NX + t) * DD + d];
    else        v = mem[(size_t)d * MMEM + (t - NX)];   // mem[0, d, t-NX]
    g_XM[idx] = __float2half(v);
}

__global__ void cvt_w_half(const float* __restrict__ w) {
    size_t idx = (size_t)blockIdx.x * blockDim.x + threadIdx.x;
    if (idx < (size_t)D3 * DD) g_W[idx] = __float2half(w[idx]);
}

// ---------------------------------------------------------------------------
// NT GEMM: C[m,n] = alpha * sum_k A[m*lda+k] * B[n*ldb+k]
// CTA 128x128, 4 warps (2m x 2n), warp tile 64x64, BK=64 (4 k16-steps).
// 128 threads -> 2 CTAs/SM (73.7KB smem, 182 regs): two independent barrier
// domains per SM so one CTA's MMA stream covers the other's stage boundary.
// Same per-warp core as round 11 (2-stage cp.async + 2-deep frag pipeline).
// ---------------------------------------------------------------------------
#define NTS   72
#define STG   (128 * NTS)                      // halves per tile per stage
#define GEMM_SMEM (4 * STG * 2)                // 73728 bytes (A+B, 2 stages)

template <typename CT>
__global__ __launch_bounds__(128, 2)
void gemm_nt_big(const __half* __restrict__ A, const __half* __restrict__ B,
                 CT* __restrict__ C, int Kdim,
                 int lda, int ldb, int ldc, float alpha,
                 size_t sA, size_t sB, size_t sC) {
    extern __shared__ __half sh[];
    __half* As = sh;                 // [2][STG]
    __half* Bs = sh + 2 * STG;       // [2][STG]
    A += (size_t)blockIdx.z * sA;
    B += (size_t)blockIdx.z * sB;
    C += (size_t)blockIdx.z * sC;
    const int m0 = blockIdx.y * 128;
    const int n0 = blockIdx.x * 128;
    const int tid  = threadIdx.x;
    const int lane = tid & 31;
    const int wid  = tid >> 5;             // 0..3
    const int mBase = (wid & 1) * 64;      // 2 m-warps
    const int nBase = (wid >> 1) * 64;     // 2 n-warps

    const uint32_t aSm = (uint32_t)__cvta_generic_to_shared(As);
    const uint32_t bSm = (uint32_t)__cvta_generic_to_shared(Bs);

    // global->smem: 128 rows x 64 halves per tile; 8 chunks of 16B per thread
    const int rowA = tid >> 3;             // 0..15 (+16 per c)
    const int k8   = (tid & 7) * 8;        // 0..56
    const __half* Ag = A + (size_t)(m0 + rowA) * lda + k8;
    const __half* Bg = B + (size_t)(n0 + rowA) * ldb + k8;
    const uint32_t aSt = aSm + (uint32_t)(rowA * NTS + k8) * 2;
    const uint32_t bSt = bSm + (uint32_t)(rowA * NTS + k8) * 2;
    const uint32_t rowStep = 16 * NTS * 2;

    const uint32_t aFrag = aSm + ((mBase + (lane & 15)) * NTS + 8 * (lane >> 4)) * 2;
    const uint32_t bFrag = bSm + ((nBase + (lane & 15)) * NTS + 8 * (lane >> 4)) * 2;

    float acc[4][8][4] = {};

#pragma unroll
    for (int c = 0; c < 8; c++) {
        cpasync16(aSt + c * rowStep, Ag + (size_t)c * 16 * lda);
        cpasync16(bSt + c * rowStep, Bg + (size_t)c * 16 * ldb);
    }
    cp_commit();

    uint32_t af[2][4][4], bf[2][4][4];

    const int nIter = Kdim >> 6;
    for (int t = 0; t < nIter; t++) {
        cp_wait0();
        __syncthreads();
        if (t + 1 < nIter) {
            const int k0 = (t + 1) * 64;
            const uint32_t ao = aSt + ((t + 1) & 1) * STG * 2;
            const uint32_t bo = bSt + ((t + 1) & 1) * STG * 2;
#pragma unroll
            for (int c = 0; c < 8; c++) {
                cpasync16(ao + c * rowStep, Ag + (size_t)c * 16 * lda + k0);
                cpasync16(bo + c * rowStep, Bg + (size_t)c * 16 * ldb + k0);
            }
            cp_commit();
        }
        const uint32_t aO = aFrag + (t & 1) * STG * 2;
        const uint32_t bO = bFrag + (t & 1) * STG * 2;

#pragma unroll
        for (int mi = 0; mi < 4; mi++) ldsm4(af[0][mi], aO + (mi * 16 * NTS) * 2);
#pragma unroll
        for (int u = 0; u < 4; u++)    ldsm4(bf[0][u],  bO + (u * 16 * NTS) * 2);
#pragma unroll
        for (int s = 0; s < 4; s++) {
            const int cur = s & 1, nxt = cur ^ 1;
            if (s < 3) {
#pragma unroll
                for (int mi = 0; mi < 4; mi++)
                    ldsm4(af[nxt][mi], aO + (mi * 16 * NTS + (s + 1) * 16) * 2);
#pragma unroll
                for (int u = 0; u < 4; u++)
                    ldsm4(bf[nxt][u],  bO + (u * 16 * NTS + (s + 1) * 16) * 2);
            }
#pragma unroll
            for (int mi = 0; mi < 4; mi++)
#pragma unroll
                for (int ni = 0; ni < 8; ni++) {
                    // x4 regs: r0=(n+0,k0) r1=(n+8,k0) r2=(n+0,k8) r3=(n+8,k8)
                    uint32_t bb[2] = { bf[cur][ni >> 1][ni & 1],
                                       bf[cur][ni >> 1][(ni & 1) + 2] };
                    mma_f16(acc[mi][ni], af[cur][mi], bb);
                }
        }
    }

    const int g = lane >> 2, tg = lane & 3;
#pragma unroll
    for (int mi = 0; mi < 4; mi++) {
        int r0 = m0 + mBase + mi * 16 + g;
#pragma unroll
        for (int ni = 0; ni < 8; ni++) {
            int cb = n0 + nBase + ni * 8 + 2 * tg;
            if constexpr (sizeof(CT) == 2) {
                __half2 v0 = __floats2half2_rn(alpha * acc[mi][ni][0], alpha * acc[mi][ni][1]);
                __half2 v1 = __floats2half2_rn(alpha * acc[mi][ni][2], alpha * acc[mi][ni][3]);
                *reinterpret_cast<__half2*>((__half*)C + (size_t)r0 * ldc + cb) = v0;
                *reinterpret_cast<__half2*>((__half*)C + (size_t)(r0 + 8) * ldc + cb) = v1;
            } else {
                float2 v0 = make_float2(alpha * acc[mi][ni][0], alpha * acc[mi][ni][1]);
                float2 v1 = make_float2(alpha * acc[mi][ni][2], alpha * acc[mi][ni][3]);
                *reinterpret_cast<float2*>((float*)C + (size_t)r0 * ldc + cb) = v0;
                *reinterpret_cast<float2*>((float*)C + (size_t)(r0 + 8) * ldc + cb) = v1;
            }
        }
    }
}

// ---------------------------------------------------------------------------
// TN GEMM: C[m,n] = sum_k A[k*lda+m] * B[k*ldb+n], C fp32.
// CTA 128x128, 4 warps (2m x 2n), warp tile 64x64, BK=64.
// smem [k][m]/[k][n] stride 136; trans-ldmatrix (round-3 verified maps).
// 128 threads -> 2 CTAs/SM (69.6KB smem).
// ---------------------------------------------------------------------------
#define TNS   136
#define TSTG  (64 * TNS)                        // halves per tile per stage
#define TGEMM_SMEM (4 * TSTG * 2)               // 69632 bytes

__global__ __launch_bounds__(128, 2)
void gemm_tn_big(const __half* __restrict__ A, const __half* __restrict__ B,
                 float* __restrict__ C, int Kdim,
                 int lda, int ldb, int ldc,
                 size_t sA, size_t sB, size_t sC) {
    extern __shared__ __half sh[];
    __half* As = sh;                  // [2][TSTG]
    __half* Bs = sh + 2 * TSTG;       // [2][TSTG]
    A += (size_t)blockIdx.z * sA;
    B += (size_t)blockIdx.z * sB;
    C += (size_t)blockIdx.z * sC;
    const int m0 = blockIdx.y * 128;
    const int n0 = blockIdx.x * 128;
    const int tid  = threadIdx.x;
    const int lane = tid & 31;
    const int wid  = tid >> 5;
    const int mBase = (wid & 1) * 64;
    const int nBase = (wid >> 1) * 64;

    const uint32_t aSm = (uint32_t)__cvta_generic_to_shared(As);
    const uint32_t bSm = (uint32_t)__cvta_generic_to_shared(Bs);

    // global->smem: 64 k-rows x 128 halves per tile; 8 chunks of 16B per thread
    const int arow = tid >> 4;             // 0..7 (+8 per c)
    const int acol = (tid & 15) * 8;       // halves 0..120
    const __half* Ag = A + (size_t)arow * lda + m0 + acol;
    const __half* Bg = B + (size_t)arow * ldb + n0 + acol;
    const uint32_t aSt = aSm + (uint32_t)(arow * TNS + acol) * 2;
    const uint32_t bSt = bSm + (uint32_t)(arow * TNS + acol) * 2;
    const uint32_t krowStep = 8 * TNS * 2;

    // trans-ldmatrix lane bases (round-3 verified mappings)
    // A frags: (k0,m0),(k0,m8),(k8,m0),(k8,m8)
    const uint32_t aFrag = aSm +
        (((lane & 7) + 8 * (lane >> 4)) * TNS + mBase + 8 * ((lane >> 3) & 1)) * 2;
    // B frags: (k0,n0),(k8,n0),(k0,n8),(k8,n8)
    const uint32_t bFrag = bSm +
        (((lane & 7) + 8 * ((lane >> 3) & 1)) * TNS + nBase + 8 * (lane >> 4)) * 2;

    float acc[4][8][4] = {};

#pragma unroll
    for (int c = 0; c < 8; c++) {
        cpasync16(aSt + c * krowStep, Ag + (size_t)c * 8 * lda);
        cpasync16(bSt + c * krowStep, Bg + (size_t)c * 8 * ldb);
    }
    cp_commit();

    uint32_t af[2][4][4], bf[2][4][4];

    const int nIter = Kdim >> 6;
    for (int t = 0; t < nIter; t++) {
        cp_wait0();
        __syncthreads();
        if (t + 1 < nIter) {
            const size_t k0 = (size_t)(t + 1) * 64;
            const uint32_t ao = aSt + ((t + 1) & 1) * TSTG * 2;
            const uint32_t bo = bSt + ((t + 1) & 1) * TSTG * 2;
#pragma unroll
            for (int c = 0; c < 8; c++) {
                cpasync16(ao + c * krowStep, Ag + (k0 + c * 8) * lda);
                cpasync16(bo + c * krowStep, Bg + (k0 + c * 8) * ldb);
            }
            cp_commit();
        }
        const uint32_t aO = aFrag + (t & 1) * TSTG * 2;
        const uint32_t bO = bFrag + (t & 1) * TSTG * 2;

#pragma unroll
        for (int mi = 0; mi < 4; mi++) ldsm4t(af[0][mi], aO + (mi * 16) * 2);
#pragma unroll
        for (int u = 0; u < 4; u++)    ldsm4t(bf[0][u],  bO + (u * 16) * 2);
#pragma unroll
        for (int s = 0; s < 4; s++) {
            const int cur = s & 1, nxt = cur ^ 1;
            if (s < 3) {
#pragma unroll
                for (int mi = 0; mi < 4; mi++)
                    ldsm4t(af[nxt][mi], aO + ((s + 1) * 16 * TNS + mi * 16) * 2);
#pragma unroll
                for (int u = 0; u < 4; u++)
                    ldsm4t(bf[nxt][u],  bO + ((s + 1) * 16 * TNS + u * 16) * 2);
            }
#pragma unroll
            for (int mi = 0; mi < 4; mi++)
#pragma unroll
                for (int ni = 0; ni < 8; ni++) {
                    // x4 regs: r0=(k0,n+0) r1=(k8,n+0) r2=(k0,n+8) r3=(k8,n+8)
                    uint32_t bb[2] = { bf[cur][ni >> 1][2 * (ni & 1)],
                                       bf[cur][ni >> 1][2 * (ni & 1) + 1] };
                    mma_f16(acc[mi][ni], af[cur][mi], bb);
                }
        }
    }

    const int g = lane >> 2, tg = lane & 3;
#pragma unroll
    for (int mi = 0; mi < 4; mi++) {
        int r0 = m0 + mBase + mi * 16 + g;
#pragma unroll
        for (int ni = 0; ni < 8; ni++) {
            int cb = n0 + nBase + ni * 8 + 2 * tg;
            float2 v0 = make_float2(acc[mi][ni][0], acc[mi][ni][1]);
            float2 v1 = make_float2(acc[mi][ni][2], acc[mi][ni][3]);
            *reinterpret_cast<float2*>(C + (size_t)r0 * ldc + cb) = v0;
            *reinterpret_cast<float2*>(C + (size_t)(r0 + 8) * ldc + cb) = v1;
        }
    }
}

// ---------------------------------------------------------------------------
// Row softmax over T=2304 columns: read fp32 logits, write fp16 probs.
// ---------------------------------------------------------------------------
__global__ __launch_bounds__(256)
void softmax_rows_kernel(const float* __restrict__ S, __half* __restrict__ P) {
    const float* row = S + (size_t)blockIdx.x * TT;
    __half* prow = P + (size_t)blockIdx.x * TT;
    const int tid = threadIdx.x;
    __shared__ float red[8];

    float v[9];
    float lmax = -1e30f;
#pragma unroll
    for (int it = 0; it < 9; it++) {
        v[it] = row[tid + it * 256];
        lmax = fmaxf(lmax, v[it]);
    }
#pragma unroll
    for (int o = 16; o; o >>= 1)
        lmax = fmaxf(lmax, __shfl_xor_sync(0xffffffffu, lmax, o));
    if ((tid & 31) == 0) red[tid >> 5] = lmax;
    __syncthreads();
    float m = red[0];
#pragma unroll
    for (int w = 1; w < 8; w++) m = fmaxf(m, red[w]);

    float e[9];
    float lsum = 0.f;
#pragma unroll
    for (int it = 0; it < 9; it++) {
        e[it] = __expf(v[it] - m);
        lsum += e[it];
    }
#pragma unroll
    for (int o = 16; o; o >>= 1)
        lsum += __shfl_xor_sync(0xffffffffu, lsum, o);
    __syncthreads();
    if ((tid & 31) == 0) red[tid >> 5] = lsum;
    __syncthreads();
    float Z = 0.f;
#pragma unroll
    for (int w = 0; w < 8; w++) Z += red[w];
    float inv = 1.0f / Z;
#pragma unroll
    for (int it = 0; it < 9; it++)
        prow[tid + it * 256] = __float2half(e[it] * inv);
}

// ---------------------------------------------------------------------------
// Launch: prep -> QKV -> S[j,i]=Q_j.K_i/sqrt(D) -> row softmax -> out = P^T V
// ---------------------------------------------------------------------------
extern "C" void kernel_launch(void* const* d_in, const int* in_sizes, int n_in,
                              void* d_out, int out_size) {
    (void)in_sizes; (void)n_in; (void)out_size;
    const float* x   = (const float*)d_in[0];
    const float* mem = (const float*)d_in[1];
    const float* w   = (const float*)d_in[2];
    float* out = (float*)d_out;

    __half *XM = nullptr, *W = nullptr, *QKV = nullptr, *P = nullptr;
    float *S = nullptr;
    cudaGetSymbolAddress((void**)&XM,  g_XM);
    cudaGetSymbolAddress((void**)&W,   g_W);
    cudaGetSymbolAddress((void**)&QKV, g_QKV);
    cudaGetSymbolAddress((void**)&S,   g_S);
    cudaGetSymbolAddress((void**)&P,   g_P);

    cudaFuncSetAttribute(gemm_nt_big<__half>,
                         cudaFuncAttributeMaxDynamicSharedMemorySize, GEMM_SMEM);
    cudaFuncSetAttribute(gemm_nt_big<float>,
                         cudaFuncAttributeMaxDynamicSharedMemorySize, GEMM_SMEM);
    cudaFuncSetAttribute(gemm_tn_big,
                         cudaFuncAttributeMaxDynamicSharedMemorySize, TGEMM_SMEM);

    // 1) prep fp16 inputs
    {
        size_t total = (size_t)BATCH * TT * DD;
        build_xm_half<<<(unsigned)((total + 255) / 256), 256>>>(x, mem);
        size_t wtot = (size_t)D3 * DD;
        cvt_w_half<<<(unsigned)((wtot + 255) / 256), 256>>>(w);
    }
    // 2) QKV = XM @ W^T   (M=18432, N=1536, K=512), fp16 out
    {
        dim3 grid(D3 / 128, (BATCH * TT) / 128, 1);
        gemm_nt_big<__half><<<grid, 128, GEMM_SMEM>>>(XM, W, QKV, DD,
                                                      DD, DD, D3, 1.0f, 0, 0, 0);
    }
    // 3) S[j,i] = Q_j . K_i / sqrt(D)  (A=Q rows, B=K rows), fp32 out
    {
        dim3 grid(TT / 128, TT / 128, BATCH);
        const float scale = 0.044194173824159216f;  // 1/sqrt(512)
        gemm_nt_big<float><<<grid, 128, GEMM_SMEM>>>(QKV, QKV + DD, S, DD,
                                                     D3, D3, TT, scale,
                                                     (size_t)TT * D3, (size_t)TT * D3,
                                                     (size_t)TT * TT);
    }
    // 4) row softmax: fp32 S -> fp16 P
    softmax_rows_kernel<<<BATCH * TT, 256>>>(S, P);
    // 5) out[i,d] = sum_j P[j,i] * V[j,d]   (TN; M=2304, N=512, K=2304)
    {
        dim3 grid(DD / 128, TT / 128, BATCH);
        gemm_tn_big<<<grid, 128, TGEMM_SMEM>>>(P, QKV + 2 * DD, out, TT,
                                               TT, D3, DD,
                                               (size_t)TT * TT, (size_t)TT * D3,
                                               (size_t)TT * DD);
    }
}

// round 14
// speedup vs baseline: 1.4452x; 1.0040x over previous
#include <cuda_runtime.h>
#include <cuda_fp16.h>
#include <math.h>
#include <stdint.h>

// Problem shape constants
#define BATCH 8
#define NX    2048
#define MMEM  256
#define TT    2304          // NX + MMEM
#define DD    512
#define D3    1536          // 3*DD

// Scratch (allocation-free: __device__ globals, 128B-aligned)
__device__ __align__(128) __half g_XM [(size_t)BATCH * TT * DD];   // 18.9 MB
__device__ __align__(128) __half g_W  [(size_t)D3 * DD];           //  1.5 MB
__device__ __align__(128) __half g_QKV[(size_t)BATCH * TT * D3];   // 56.6 MB
__device__ __align__(128) float  g_S  [(size_t)BATCH * TT * TT];   // 169.9 MB  S[j,i]
__device__ __align__(128) __half g_P  [(size_t)BATCH * TT * TT];   // 85.0 MB   P[j,i]

// ---------------------------------------------------------------------------
// PTX helpers (sm_100 base ISA: mma.sync / ldmatrix / cp.async)
// ---------------------------------------------------------------------------
__device__ __forceinline__ void mma_f16(float* c, const uint32_t* a, const uint32_t* b) {
    asm volatile(
        "mma.sync.aligned.m16n8k16.row.col.f32.f16.f16.f32 "
        "{%0,%1,%2,%3}, {%4,%5,%6,%7}, {%8,%9}, {%0,%1,%2,%3};\n"
        : "+f"(c[0]), "+f"(c[1]), "+f"(c[2]), "+f"(c[3])
        : "r"(a[0]), "r"(a[1]), "r"(a[2]), "r"(a[3]), "r"(b[0]), "r"(b[1]));
}

__device__ __forceinline__ void ldsm4(uint32_t* r, uint32_t addr) {
    asm volatile("ldmatrix.sync.aligned.m8n8.x4.shared.b16 {%0,%1,%2,%3}, [%4];"
                 : "=r"(r[0]), "=r"(r[1]), "=r"(r[2]), "=r"(r[3]) : "r"(addr));
}

__device__ __forceinline__ void ldsm4t(uint32_t* r, uint32_t addr) {
    asm volatile("ldmatrix.sync.aligned.m8n8.x4.trans.shared.b16 {%0,%1,%2,%3}, [%4];"
                 : "=r"(r[0]), "=r"(r[1]), "=r"(r[2]), "=r"(r[3]) : "r"(addr));
}

__device__ __forceinline__ void cpasync16(uint32_t s, const void* g) {
    asm volatile("cp.async.cg.shared.global [%0], [%1], 16;\n" :: "r"(s), "l"(g));
}
__device__ __forceinline__ void cp_commit() {
    asm volatile("cp.async.commit_group;\n" ::: "memory");
}
__device__ __forceinline__ void cp_wait0() {
    asm volatile("cp.async.wait_group 0;\n" ::: "memory");
}

// ---------------------------------------------------------------------------
// Input prep: XM = concat(x, mem^T) in fp16;  W -> fp16
// ---------------------------------------------------------------------------
__global__ void build_xm_half(const float* __restrict__ x,
                              const float* __restrict__ mem) {
    size_t idx = (size_t)blockIdx.x * blockDim.x + threadIdx.x;
    const size_t total = (size_t)BATCH * TT * DD;
    if (idx >= total) return;
    int d = (int)(idx % DD);
    size_t bt = idx / DD;
    int t = (int)(bt % TT);
    int b = (int)(bt / TT);
    float v;
    if (t < NX) v = x[((size_t)b * NX + t) * DD + d];
    else        v = mem[(size_t)d * MMEM + (t - NX)];   // mem[0, d, t-NX]
    g_XM[idx] = __float2half(v);
}

__global__ void cvt_w_half(const float* __restrict__ w) {
    size_t idx = (size_t)blockIdx.x * blockDim.x + threadIdx.x;
    if (idx < (size_t)D3 * DD) g_W[idx] = __float2half(w[idx]);
}

// ---------------------------------------------------------------------------
// NT GEMM: C[m,n] = alpha * sum_k A[m*lda+k] * B[n*ldb+k]
// CTA 128x128, 4 warps (2m x 2n), warp tile 64x64, BK=64 (4 k16-steps).
// SINGLE-buffered fragments (32 regs) -> ~150 regs -> 3 CTAs/SM: latency is
// covered by TLP (3 warps/SMSP, 3 independent barrier domains), not ILP.
// 2-stage cp.async smem pipeline; stride 72 halves (conflict-free).
// ---------------------------------------------------------------------------
#define NTS   72
#define STG   (128 * NTS)                      // halves per tile per stage
#define GEMM_SMEM (4 * STG * 2)                // 73728 bytes (A+B, 2 stages)

template <typename CT>
__global__ __launch_bounds__(128, 3)
void gemm_nt_big(const __half* __restrict__ A, const __half* __restrict__ B,
                 CT* __restrict__ C, int Kdim,
                 int lda, int ldb, int ldc, float alpha,
                 size_t sA, size_t sB, size_t sC) {
    extern __shared__ __half sh[];
    __half* As = sh;                 // [2][STG]
    __half* Bs = sh + 2 * STG;       // [2][STG]
    A += (size_t)blockIdx.z * sA;
    B += (size_t)blockIdx.z * sB;
    C += (size_t)blockIdx.z * sC;
    const int m0 = blockIdx.y * 128;
    const int n0 = blockIdx.x * 128;
    const int tid  = threadIdx.x;
    const int lane = tid & 31;
    const int wid  = tid >> 5;             // 0..3
    const int mBase = (wid & 1) * 64;      // 2 m-warps
    const int nBase = (wid >> 1) * 64;     // 2 n-warps

    const uint32_t aSm = (uint32_t)__cvta_generic_to_shared(As);
    const uint32_t bSm = (uint32_t)__cvta_generic_to_shared(Bs);

    // global->smem: 128 rows x 64 halves per tile; 8 chunks of 16B per thread
    const int rowA = tid >> 3;             // 0..15 (+16 per c)
    const int k8   = (tid & 7) * 8;        // 0..56
    const __half* Ag = A + (size_t)(m0 + rowA) * lda + k8;
    const __half* Bg = B + (size_t)(n0 + rowA) * ldb + k8;
    const uint32_t aSt = aSm + (uint32_t)(rowA * NTS + k8) * 2;
    const uint32_t bSt = bSm + (uint32_t)(rowA * NTS + k8) * 2;
    const uint32_t rowStep = 16 * NTS * 2;

    const uint32_t aFrag = aSm + ((mBase + (lane & 15)) * NTS + 8 * (lane >> 4)) * 2;
    const uint32_t bFrag = bSm + ((nBase + (lane & 15)) * NTS + 8 * (lane >> 4)) * 2;

    float acc[4][8][4] = {};

#pragma unroll
    for (int c = 0; c < 8; c++) {
        cpasync16(aSt + c * rowStep, Ag + (size_t)c * 16 * lda);
        cpasync16(bSt + c * rowStep, Bg + (size_t)c * 16 * ldb);
    }
    cp_commit();

    const int nIter = Kdim >> 6;
    for (int t = 0; t < nIter; t++) {
        cp_wait0();
        __syncthreads();
        if (t + 1 < nIter) {
            const int k0 = (t + 1) * 64;
            const uint32_t ao = aSt + ((t + 1) & 1) * STG * 2;
            const uint32_t bo = bSt + ((t + 1) & 1) * STG * 2;
#pragma unroll
            for (int c = 0; c < 8; c++) {
                cpasync16(ao + c * rowStep, Ag + (size_t)c * 16 * lda + k0);
                cpasync16(bo + c * rowStep, Bg + (size_t)c * 16 * ldb + k0);
            }
            cp_commit();
        }
        const uint32_t aO = aFrag + (t & 1) * STG * 2;
        const uint32_t bO = bFrag + (t & 1) * STG * 2;

        // single-buffered fragments: per k16-step, 8 ldsm then 32 MMAs.
        // Cross-warp TLP (3 warps/SMSP) covers the ldsm->mma latency.
#pragma unroll
        for (int s = 0; s < 4; s++) {
            uint32_t af[4][4], bf[4][4];
#pragma unroll
            for (int mi = 0; mi < 4; mi++)
                ldsm4(af[mi], aO + (mi * 16 * NTS + s * 16) * 2);
#pragma unroll
            for (int u = 0; u < 4; u++)
                ldsm4(bf[u],  bO + (u * 16 * NTS + s * 16) * 2);
#pragma unroll
            for (int mi = 0; mi < 4; mi++)
#pragma unroll
                for (int ni = 0; ni < 8; ni++) {
                    // x4 regs: r0=(n+0,k0) r1=(n+8,k0) r2=(n+0,k8) r3=(n+8,k8)
                    uint32_t bb[2] = { bf[ni >> 1][ni & 1],
                                       bf[ni >> 1][(ni & 1) + 2] };
                    mma_f16(acc[mi][ni], af[mi], bb);
                }
        }
    }

    const int g = lane >> 2, tg = lane & 3;
#pragma unroll
    for (int mi = 0; mi < 4; mi++) {
        int r0 = m0 + mBase + mi * 16 + g;
#pragma unroll
        for (int ni = 0; ni < 8; ni++) {
            int cb = n0 + nBase + ni * 8 + 2 * tg;
            if constexpr (sizeof(CT) == 2) {
                __half2 v0 = __floats2half2_rn(alpha * acc[mi][ni][0], alpha * acc[mi][ni][1]);
                __half2 v1 = __floats2half2_rn(alpha * acc[mi][ni][2], alpha * acc[mi][ni][3]);
                *reinterpret_cast<__half2*>((__half*)C + (size_t)r0 * ldc + cb) = v0;
                *reinterpret_cast<__half2*>((__half*)C + (size_t)(r0 + 8) * ldc + cb) = v1;
            } else {
                float2 v0 = make_float2(alpha * acc[mi][ni][0], alpha * acc[mi][ni][1]);
                float2 v1 = make_float2(alpha * acc[mi][ni][2], alpha * acc[mi][ni][3]);
                *reinterpret_cast<float2*>((float*)C + (size_t)r0 * ldc + cb) = v0;
                *reinterpret_cast<float2*>((float*)C + (size_t)(r0 + 8) * ldc + cb) = v1;
            }
        }
    }
}

// ---------------------------------------------------------------------------
// TN GEMM: C[m,n] = sum_k A[k*lda+m] * B[k*ldb+n], C fp32.
// CTA 128x128, 4 warps (2m x 2n), warp tile 64x64, BK=64.
// Single-buffered fragments -> 3 CTAs/SM. smem [k][m]/[k][n] stride 136;
// trans-ldmatrix (round-3 verified maps); 2-stage cp.async pipeline.
// ---------------------------------------------------------------------------
#define TNS   136
#define TSTG  (64 * TNS)                        // halves per tile per stage
#define TGEMM_SMEM (4 * TSTG * 2)               // 69632 bytes

__global__ __launch_bounds__(128, 3)
void gemm_tn_big(const __half* __restrict__ A, const __half* __restrict__ B,
                 float* __restrict__ C, int Kdim,
                 int lda, int ldb, int ldc,
                 size_t sA, size_t sB, size_t sC) {
    extern __shared__ __half sh[];
    __half* As = sh;                  // [2][TSTG]
    __half* Bs = sh + 2 * TSTG;       // [2][TSTG]
    A += (size_t)blockIdx.z * sA;
    B += (size_t)blockIdx.z * sB;
    C += (size_t)blockIdx.z * sC;
    const int m0 = blockIdx.y * 128;
    const int n0 = blockIdx.x * 128;
    const int tid  = threadIdx.x;
    const int lane = tid & 31;
    const int wid  = tid >> 5;
    const int mBase = (wid & 1) * 64;
    const int nBase = (wid >> 1) * 64;

    const uint32_t aSm = (uint32_t)__cvta_generic_to_shared(As);
    const uint32_t bSm = (uint32_t)__cvta_generic_to_shared(Bs);

    // global->smem: 64 k-rows x 128 halves per tile; 8 chunks of 16B per thread
    const int arow = tid >> 4;             // 0..7 (+8 per c)
    const int acol = (tid & 15) * 8;       // halves 0..120
    const __half* Ag = A + (size_t)arow * lda + m0 + acol;
    const __half* Bg = B + (size_t)arow * ldb + n0 + acol;
    const uint32_t aSt = aSm + (uint32_t)(arow * TNS + acol) * 2;
    const uint32_t bSt = bSm + (uint32_t)(arow * TNS + acol) * 2;
    const uint32_t krowStep = 8 * TNS * 2;

    // trans-ldmatrix lane bases (round-3 verified mappings)
    // A frags: (k0,m0),(k0,m8),(k8,m0),(k8,m8)
    const uint32_t aFrag = aSm +
        (((lane & 7) + 8 * (lane >> 4)) * TNS + mBase + 8 * ((lane >> 3) & 1)) * 2;
    // B frags: (k0,n0),(k8,n0),(k0,n8),(k8,n8)
    const uint32_t bFrag = bSm +
        (((lane & 7) + 8 * ((lane >> 3) & 1)) * TNS + nBase + 8 * (lane >> 4)) * 2;

    float acc[4][8][4] = {};

#pragma unroll
    for (int c = 0; c < 8; c++) {
        cpasync16(aSt + c * krowStep, Ag + (size_t)c * 8 * lda);
        cpasync16(bSt + c * krowStep, Bg + (size_t)c * 8 * ldb);
    }
    cp_commit();

    const int nIter = Kdim >> 6;
    for (int t = 0; t < nIter; t++) {
        cp_wait0();
        __syncthreads();
        if (t + 1 < nIter) {
            const size_t k0 = (size_t)(t + 1) * 64;
            const uint32_t ao = aSt + ((t + 1) & 1) * TSTG * 2;
            const uint32_t bo = bSt + ((t + 1) & 1) * TSTG * 2;
#pragma unroll
            for (int c = 0; c < 8; c++) {
                cpasync16(ao + c * krowStep, Ag + (k0 + c * 8) * lda);
                cpasync16(bo + c * krowStep, Bg + (k0 + c * 8) * ldb);
            }
            cp_commit();
        }
        const uint32_t aO = aFrag + (t & 1) * TSTG * 2;
        const uint32_t bO = bFrag + (t & 1) * TSTG * 2;

#pragma unroll
        for (int s = 0; s < 4; s++) {
            uint32_t af[4][4], bf[4][4];
#pragma unroll
            for (int mi = 0; mi < 4; mi++)
                ldsm4t(af[mi], aO + (s * 16 * TNS + mi * 16) * 2);
#pragma unroll
            for (int u = 0; u < 4; u++)
                ldsm4t(bf[u],  bO + (s * 16 * TNS + u * 16) * 2);
#pragma unroll
            for (int mi = 0; mi < 4; mi++)
#pragma unroll
                for (int ni = 0; ni < 8; ni++) {
                    // x4 regs: r0=(k0,n+0) r1=(k8,n+0) r2=(k0,n+8) r3=(k8,n+8)
                    uint32_t bb[2] = { bf[ni >> 1][2 * (ni & 1)],
                                       bf[ni >> 1][2 * (ni & 1) + 1] };
                    mma_f16(acc[mi][ni], af[mi], bb);
                }
        }
    }

    const int g = lane >> 2, tg = lane & 3;
#pragma unroll
    for (int mi = 0; mi < 4; mi++) {
        int r0 = m0 + mBase + mi * 16 + g;
#pragma unroll
        for (int ni = 0; ni < 8; ni++) {
            int cb = n0 + nBase + ni * 8 + 2 * tg;
            float2 v0 = make_float2(acc[mi][ni][0], acc[mi][ni][1]);
            float2 v1 = make_float2(acc[mi][ni][2], acc[mi][ni][3]);
            *reinterpret_cast<float2*>(C + (size_t)r0 * ldc + cb) = v0;
            *reinterpret_cast<float2*>(C + (size_t)(r0 + 8) * ldc + cb) = v1;
        }
    }
}

// ---------------------------------------------------------------------------
// Row softmax over T=2304 columns: read fp32 logits, write fp16 probs.
// ---------------------------------------------------------------------------
__global__ __launch_bounds__(256)
void softmax_rows_kernel(const float* __restrict__ S, __half* __restrict__ P) {
    const float* row = S + (size_t)blockIdx.x * TT;
    __half* prow = P + (size_t)blockIdx.x * TT;
    const int tid = threadIdx.x;
    __shared__ float red[8];

    float v[9];
    float lmax = -1e30f;
#pragma unroll
    for (int it = 0; it < 9; it++) {
        v[it] = row[tid + it * 256];
        lmax = fmaxf(lmax, v[it]);
    }
#pragma unroll
    for (int o = 16; o; o >>= 1)
        lmax = fmaxf(lmax, __shfl_xor_sync(0xffffffffu, lmax, o));
    if ((tid & 31) == 0) red[tid >> 5] = lmax;
    __syncthreads();
    float m = red[0];
#pragma unroll
    for (int w = 1; w < 8; w++) m = fmaxf(m, red[w]);

    float e[9];
    float lsum = 0.f;
#pragma unroll
    for (int it = 0; it < 9; it++) {
        e[it] = __expf(v[it] - m);
        lsum += e[it];
    }
#pragma unroll
    for (int o = 16; o; o >>= 1)
        lsum += __shfl_xor_sync(0xffffffffu, lsum, o);
    __syncthreads();
    if ((tid & 31) == 0) red[tid >> 5] = lsum;
    __syncthreads();
    float Z = 0.f;
#pragma unroll
    for (int w = 0; w < 8; w++) Z += red[w];
    float inv = 1.0f / Z;
#pragma unroll
    for (int it = 0; it < 9; it++)
        prow[tid + it * 256] = __float2half(e[it] * inv);
}

// ---------------------------------------------------------------------------
// Launch: prep -> QKV -> S[j,i]=Q_j.K_i/sqrt(D) -> row softmax -> out = P^T V
// ---------------------------------------------------------------------------
extern "C" void kernel_launch(void* const* d_in, const int* in_sizes, int n_in,
                              void* d_out, int out_size) {
    (void)in_sizes; (void)n_in; (void)out_size;
    const float* x   = (const float*)d_in[0];
    const float* mem = (const float*)d_in[1];
    const float* w   = (const float*)d_in[2];
    float* out = (float*)d_out;

    __half *XM = nullptr, *W = nullptr, *QKV = nullptr, *P = nullptr;
    float *S = nullptr;
    cudaGetSymbolAddress((void**)&XM,  g_XM);
    cudaGetSymbolAddress((void**)&W,   g_W);
    cudaGetSymbolAddress((void**)&QKV, g_QKV);
    cudaGetSymbolAddress((void**)&S,   g_S);
    cudaGetSymbolAddress((void**)&P,   g_P);

    cudaFuncSetAttribute(gemm_nt_big<__half>,
                         cudaFuncAttributeMaxDynamicSharedMemorySize, GEMM_SMEM);
    cudaFuncSetAttribute(gemm_nt_big<float>,
                         cudaFuncAttributeMaxDynamicSharedMemorySize, GEMM_SMEM);
    cudaFuncSetAttribute(gemm_tn_big,
                         cudaFuncAttributeMaxDynamicSharedMemorySize, TGEMM_SMEM);

    // 1) prep fp16 inputs
    {
        size_t total = (size_t)BATCH * TT * DD;
        build_xm_half<<<(unsigned)((total + 255) / 256), 256>>>(x, mem);
        size_t wtot = (size_t)D3 * DD;
        cvt_w_half<<<(unsigned)((wtot + 255) / 256), 256>>>(w);
    }
    // 2) QKV = XM @ W^T   (M=18432, N=1536, K=512), fp16 out
    {
        dim3 grid(D3 / 128, (BATCH * TT) / 128, 1);
        gemm_nt_big<__half><<<grid, 128, GEMM_SMEM>>>(XM, W, QKV, DD,
                                                      DD, DD, D3, 1.0f, 0, 0, 0);
    }
    // 3) S[j,i] = Q_j . K_i / sqrt(D)  (A=Q rows, B=K rows), fp32 out
    {
        dim3 grid(TT / 128, TT / 128, BATCH);
        const float scale = 0.044194173824159216f;  // 1/sqrt(512)
        gemm_nt_big<float><<<grid, 128, GEMM_SMEM>>>(QKV, QKV + DD, S, DD,
                                                     D3, D3, TT, scale,
                                                     (size_t)TT * D3, (size_t)TT * D3,
                                                     (size_t)TT * TT);
    }
    // 4) row softmax: fp32 S -> fp16 P
    softmax_rows_kernel<<<BATCH * TT, 256>>>(S, P);
    // 5) out[i,d] = sum_j P[j,i] * V[j,d]   (TN; M=2304, N=512, K=2304)
    {
        dim3 grid(DD / 128, TT / 128, BATCH);
        gemm_tn_big<<<grid, 128, TGEMM_SMEM>>>(P, QKV + 2 * DD, out, TT,
                                               TT, D3, DD,
                                               (size_t)TT * TT, (size_t)TT * D3,
                                               (size_t)TT * DD);
    }
}

// round 15
// speedup vs baseline: 1.4671x; 1.0152x over previous
#include <cuda_runtime.h>
#include <cuda_fp16.h>
#include <math.h>
#include <stdint.h>

// Problem shape constants
#define BATCH 8
#define NX    2048
#define MMEM  256
#define TT    2304          // NX + MMEM
#define DD    512
#define D3    1536          // 3*DD

// Scratch (allocation-free: __device__ globals, 128B-aligned)
__device__ __align__(128) __half g_XM [(size_t)BATCH * TT * DD];   // 18.9 MB
__device__ __align__(128) __half g_W  [(size_t)D3 * DD];           //  1.5 MB
__device__ __align__(128) __half g_QKV[(size_t)BATCH * TT * D3];   // 56.6 MB
__device__ __align__(128) __half g_S  [(size_t)BATCH * TT * TT];   // 85.0 MB  S[j,i] fp16 logits
__device__ __align__(128) __half g_P  [(size_t)BATCH * TT * TT];   // 85.0 MB  P[j,i] fp16 probs

// ---------------------------------------------------------------------------
// PTX helpers (sm_100 base ISA: mma.sync / ldmatrix / cp.async)
// ---------------------------------------------------------------------------
__device__ __forceinline__ void mma_f16(float* c, const uint32_t* a, const uint32_t* b) {
    asm volatile(
        "mma.sync.aligned.m16n8k16.row.col.f32.f16.f16.f32 "
        "{%0,%1,%2,%3}, {%4,%5,%6,%7}, {%8,%9}, {%0,%1,%2,%3};\n"
        : "+f"(c[0]), "+f"(c[1]), "+f"(c[2]), "+f"(c[3])
        : "r"(a[0]), "r"(a[1]), "r"(a[2]), "r"(a[3]), "r"(b[0]), "r"(b[1]));
}

// ldmatrix with compile-time immediate offset: no per-load address ALU.
template <int OFF>
__device__ __forceinline__ void ldsm4i(uint32_t* r, uint32_t base) {
    asm volatile("ldmatrix.sync.aligned.m8n8.x4.shared.b16 {%0,%1,%2,%3}, [%4+%5];"
                 : "=r"(r[0]), "=r"(r[1]), "=r"(r[2]), "=r"(r[3])
                 : "r"(base), "n"(OFF));
}
template <int OFF>
__device__ __forceinline__ void ldsm4ti(uint32_t* r, uint32_t base) {
    asm volatile("ldmatrix.sync.aligned.m8n8.x4.trans.shared.b16 {%0,%1,%2,%3}, [%4+%5];"
                 : "=r"(r[0]), "=r"(r[1]), "=r"(r[2]), "=r"(r[3])
                 : "r"(base), "n"(OFF));
}

__device__ __forceinline__ void cpasync16(uint32_t s, const void* g) {
    asm volatile("cp.async.cg.shared.global [%0], [%1], 16;\n" :: "r"(s), "l"(g));
}
__device__ __forceinline__ void cp_commit() {
    asm volatile("cp.async.commit_group;\n" ::: "memory");
}
__device__ __forceinline__ void cp_wait0() {
    asm volatile("cp.async.wait_group 0;\n" ::: "memory");
}

// ---------------------------------------------------------------------------
// Input prep: XM = concat(x, mem^T) in fp16;  W -> fp16
// ---------------------------------------------------------------------------
__global__ void build_xm_half(const float* __restrict__ x,
                              const float* __restrict__ mem) {
    size_t idx = (size_t)blockIdx.x * blockDim.x + threadIdx.x;
    const size_t total = (size_t)BATCH * TT * DD;
    if (idx >= total) return;
    int d = (int)(idx % DD);
    size_t bt = idx / DD;
    int t = (int)(bt % TT);
    int b = (int)(bt / TT);
    float v;
    if (t < NX) v = x[((size_t)b * NX + t) * DD + d];
    else        v = mem[(size_t)d * MMEM + (t - NX)];   // mem[0, d, t-NX]
    g_XM[idx] = __float2half(v);
}

__global__ void cvt_w_half(const float* __restrict__ w) {
    size_t idx = (size_t)blockIdx.x * blockDim.x + threadIdx.x;
    if (idx < (size_t)D3 * DD) g_W[idx] = __float2half(w[idx]);
}

// ---------------------------------------------------------------------------
// NT GEMM: C[m,n] = alpha * sum_k A[m*lda+k] * B[n*ldb+k]
// CTA 128x128, 4 warps (2m x 2n), warp tile 64x64, BK=64, 3 CTAs/SM.
// ldmatrix via immediate offsets (one fixed base per stage, zero addr ALU).
// 2-stage cp.async smem pipeline; stride 72 halves (conflict-free).
// ---------------------------------------------------------------------------
#define NTS   72
#define STG   (128 * NTS)                      // halves per tile per stage
#define GEMM_SMEM (4 * STG * 2)                // 73728 bytes (A+B, 2 stages)

#define NT_LDSA(mi, s) ldsm4i<((mi) * 16 * NTS + (s) * 16) * 2>(af[mi], aO)
#define NT_LDSB(u, s)  ldsm4i<((u) * 16 * NTS + (s) * 16) * 2>(bf[u], bO)
#define NT_STEP(s) do {                                                        \
    NT_LDSA(0, s); NT_LDSA(1, s); NT_LDSA(2, s); NT_LDSA(3, s);                \
    NT_LDSB(0, s); NT_LDSB(1, s); NT_LDSB(2, s); NT_LDSB(3, s);                \
    _Pragma("unroll")                                                          \
    for (int mi = 0; mi < 4; mi++) {                                           \
        _Pragma("unroll")                                                      \
        for (int ni = 0; ni < 8; ni++) {                                       \
            uint32_t bb[2] = { bf[ni >> 1][ni & 1], bf[ni >> 1][(ni & 1) + 2] }; \
            mma_f16(acc[mi][ni], af[mi], bb);                                  \
        }                                                                      \
    }                                                                          \
} while (0)

template <typename CT>
__global__ __launch_bounds__(128, 3)
void gemm_nt_big(const __half* __restrict__ A, const __half* __restrict__ B,
                 CT* __restrict__ C, int Kdim,
                 int lda, int ldb, int ldc, float alpha,
                 size_t sA, size_t sB, size_t sC) {
    extern __shared__ __half sh[];
    __half* As = sh;                 // [2][STG]
    __half* Bs = sh + 2 * STG;       // [2][STG]
    A += (size_t)blockIdx.z * sA;
    B += (size_t)blockIdx.z * sB;
    C += (size_t)blockIdx.z * sC;
    const int m0 = blockIdx.y * 128;
    const int n0 = blockIdx.x * 128;
    const int tid  = threadIdx.x;
    const int lane = tid & 31;
    const int wid  = tid >> 5;             // 0..3
    const int mBase = (wid & 1) * 64;      // 2 m-warps
    const int nBase = (wid >> 1) * 64;     // 2 n-warps

    const uint32_t aSm = (uint32_t)__cvta_generic_to_shared(As);
    const uint32_t bSm = (uint32_t)__cvta_generic_to_shared(Bs);

    // global->smem: 128 rows x 64 halves per tile; 8 chunks of 16B per thread
    const int rowA = tid >> 3;             // 0..15 (+16 per c)
    const int k8   = (tid & 7) * 8;        // 0..56
    const __half* Ag = A + (size_t)(m0 + rowA) * lda + k8;
    const __half* Bg = B + (size_t)(n0 + rowA) * ldb + k8;
    const uint32_t aSt = aSm + (uint32_t)(rowA * NTS + k8) * 2;
    const uint32_t bSt = bSm + (uint32_t)(rowA * NTS + k8) * 2;
    const uint32_t rowStep = 16 * NTS * 2;

    const uint32_t aFrag = aSm + ((mBase + (lane & 15)) * NTS + 8 * (lane >> 4)) * 2;
    const uint32_t bFrag = bSm + ((nBase + (lane & 15)) * NTS + 8 * (lane >> 4)) * 2;

    float acc[4][8][4] = {};

#pragma unroll
    for (int c = 0; c < 8; c++) {
        cpasync16(aSt + c * rowStep, Ag + (size_t)c * 16 * lda);
        cpasync16(bSt + c * rowStep, Bg + (size_t)c * 16 * ldb);
    }
    cp_commit();

    const int nIter = Kdim >> 6;
    for (int t = 0; t < nIter; t++) {
        cp_wait0();
        __syncthreads();
        if (t + 1 < nIter) {
            const int k0 = (t + 1) * 64;
            const uint32_t ao = aSt + ((t + 1) & 1) * STG * 2;
            const uint32_t bo = bSt + ((t + 1) & 1) * STG * 2;
#pragma unroll
            for (int c = 0; c < 8; c++) {
                cpasync16(ao + c * rowStep, Ag + (size_t)c * 16 * lda + k0);
                cpasync16(bo + c * rowStep, Bg + (size_t)c * 16 * ldb + k0);
            }
            cp_commit();
        }
        const uint32_t aO = aFrag + (t & 1) * STG * 2;
        const uint32_t bO = bFrag + (t & 1) * STG * 2;

        uint32_t af[4][4], bf[4][4];
        NT_STEP(0);
        NT_STEP(1);
        NT_STEP(2);
        NT_STEP(3);
    }

    const int g = lane >> 2, tg = lane & 3;
#pragma unroll
    for (int mi = 0; mi < 4; mi++) {
        int r0 = m0 + mBase + mi * 16 + g;
#pragma unroll
        for (int ni = 0; ni < 8; ni++) {
            int cb = n0 + nBase + ni * 8 + 2 * tg;
            if constexpr (sizeof(CT) == 2) {
                __half2 v0 = __floats2half2_rn(alpha * acc[mi][ni][0], alpha * acc[mi][ni][1]);
                __half2 v1 = __floats2half2_rn(alpha * acc[mi][ni][2], alpha * acc[mi][ni][3]);
                *reinterpret_cast<__half2*>((__half*)C + (size_t)r0 * ldc + cb) = v0;
                *reinterpret_cast<__half2*>((__half*)C + (size_t)(r0 + 8) * ldc + cb) = v1;
            } else {
                float2 v0 = make_float2(alpha * acc[mi][ni][0], alpha * acc[mi][ni][1]);
                float2 v1 = make_float2(alpha * acc[mi][ni][2], alpha * acc[mi][ni][3]);
                *reinterpret_cast<float2*>((float*)C + (size_t)r0 * ldc + cb) = v0;
                *reinterpret_cast<float2*>((float*)C + (size_t)(r0 + 8) * ldc + cb) = v1;
            }
        }
    }
}

// ---------------------------------------------------------------------------
// TN GEMM: C[m,n] = sum_k A[k*lda+m] * B[k*ldb+n], C fp32.
// CTA 128x128, 4 warps (2m x 2n), warp tile 64x64, BK=64, 3 CTAs/SM.
// smem [k][m]/[k][n] stride 136; trans-ldmatrix with immediate offsets.
// ---------------------------------------------------------------------------
#define TNS   136
#define TSTG  (64 * TNS)                        // halves per tile per stage
#define TGEMM_SMEM (4 * TSTG * 2)               // 69632 bytes

#define TN_LDSA(mi, s) ldsm4ti<((s) * 16 * TNS + (mi) * 16) * 2>(af[mi], aO)
#define TN_LDSB(u, s)  ldsm4ti<((s) * 16 * TNS + (u) * 16) * 2>(bf[u], bO)
#define TN_STEP(s) do {                                                        \
    TN_LDSA(0, s); TN_LDSA(1, s); TN_LDSA(2, s); TN_LDSA(3, s);                \
    TN_LDSB(0, s); TN_LDSB(1, s); TN_LDSB(2, s); TN_LDSB(3, s);                \
    _Pragma("unroll")                                                          \
    for (int mi = 0; mi < 4; mi++) {                                           \
        _Pragma("unroll")                                                      \
        for (int ni = 0; ni < 8; ni++) {                                       \
            uint32_t bb[2] = { bf[ni >> 1][2 * (ni & 1)], bf[ni >> 1][2 * (ni & 1) + 1] }; \
            mma_f16(acc[mi][ni], af[mi], bb);                                  \
        }                                                                      \
    }                                                                          \
} while (0)

__global__ __launch_bounds__(128, 3)
void gemm_tn_big(const __half* __restrict__ A, const __half* __restrict__ B,
                 float* __restrict__ C, int Kdim,
                 int lda, int ldb, int ldc,
                 size_t sA, size_t sB, size_t sC) {
    extern __shared__ __half sh[];
    __half* As = sh;                  // [2][TSTG]
    __half* Bs = sh + 2 * TSTG;       // [2][TSTG]
    A += (size_t)blockIdx.z * sA;
    B += (size_t)blockIdx.z * sB;
    C += (size_t)blockIdx.z * sC;
    const int m0 = blockIdx.y * 128;
    const int n0 = blockIdx.x * 128;
    const int tid  = threadIdx.x;
    const int lane = tid & 31;
    const int wid  = tid >> 5;
    const int mBase = (wid & 1) * 64;
    const int nBase = (wid >> 1) * 64;

    const uint32_t aSm = (uint32_t)__cvta_generic_to_shared(As);
    const uint32_t bSm = (uint32_t)__cvta_generic_to_shared(Bs);

    // global->smem: 64 k-rows x 128 halves per tile; 8 chunks of 16B per thread
    const int arow = tid >> 4;             // 0..7 (+8 per c)
    const int acol = (tid & 15) * 8;       // halves 0..120
    const __half* Ag = A + (size_t)arow * lda + m0 + acol;
    const __half* Bg = B + (size_t)arow * ldb + n0 + acol;
    const uint32_t aSt = aSm + (uint32_t)(arow * TNS + acol) * 2;
    const uint32_t bSt = bSm + (uint32_t)(arow * TNS + acol) * 2;
    const uint32_t krowStep = 8 * TNS * 2;

    // trans-ldmatrix lane bases (round-3 verified mappings)
    // A frags: (k0,m0),(k0,m8),(k8,m0),(k8,m8)
    const uint32_t aFrag = aSm +
        (((lane & 7) + 8 * (lane >> 4)) * TNS + mBase + 8 * ((lane >> 3) & 1)) * 2;
    // B frags: (k0,n0),(k8,n0),(k0,n8),(k8,n8)
    const uint32_t bFrag = bSm +
        (((lane & 7) + 8 * ((lane >> 3) & 1)) * TNS + nBase + 8 * (lane >> 4)) * 2;

    float acc[4][8][4] = {};

#pragma unroll
    for (int c = 0; c < 8; c++) {
        cpasync16(aSt + c * krowStep, Ag + (size_t)c * 8 * lda);
        cpasync16(bSt + c * krowStep, Bg + (size_t)c * 8 * ldb);
    }
    cp_commit();

    const int nIter = Kdim >> 6;
    for (int t = 0; t < nIter; t++) {
        cp_wait0();
        __syncthreads();
        if (t + 1 < nIter) {
            const size_t k0 = (size_t)(t + 1) * 64;
            const uint32_t ao = aSt + ((t + 1) & 1) * TSTG * 2;
            const uint32_t bo = bSt + ((t + 1) & 1) * TSTG * 2;
#pragma unroll
            for (int c = 0; c < 8; c++) {
                cpasync16(ao + c * krowStep, Ag + (k0 + c * 8) * lda);
                cpasync16(bo + c * krowStep, Bg + (k0 + c * 8) * ldb);
            }
            cp_commit();
        }
        const uint32_t aO = aFrag + (t & 1) * TSTG * 2;
        const uint32_t bO = bFrag + (t & 1) * TSTG * 2;

        uint32_t af[4][4], bf[4][4];
        TN_STEP(0);
        TN_STEP(1);
        TN_STEP(2);
        TN_STEP(3);
    }

    const int g = lane >> 2, tg = lane & 3;
#pragma unroll
    for (int mi = 0; mi < 4; mi++) {
        int r0 = m0 + mBase + mi * 16 + g;
#pragma unroll
        for (int ni = 0; ni < 8; ni++) {
            int cb = n0 + nBase + ni * 8 + 2 * tg;
            float2 v0 = make_float2(acc[mi][ni][0], acc[mi][ni][1]);
            float2 v1 = make_float2(acc[mi][ni][2], acc[mi][ni][3]);
            *reinterpret_cast<float2*>(C + (size_t)r0 * ldc + cb) = v0;
            *reinterpret_cast<float2*>(C + (size_t)(r0 + 8) * ldc + cb) = v1;
        }
    }
}

// ---------------------------------------------------------------------------
// Row softmax over T=2304 columns: read fp16 logits, write fp16 probs.
// ---------------------------------------------------------------------------
__global__ __launch_bounds__(256)
void softmax_rows_kernel(const __half* __restrict__ S, __half* __restrict__ P) {
    const __half* row = S + (size_t)blockIdx.x * TT;
    __half* prow = P + (size_t)blockIdx.x * TT;
    const int tid = threadIdx.x;
    __shared__ float red[8];

    float v[9];
    float lmax = -1e30f;
#pragma unroll
    for (int it = 0; it < 9; it++) {
        v[it] = __half2float(row[tid + it * 256]);
        lmax = fmaxf(lmax, v[it]);
    }
#pragma unroll
    for (int o = 16; o; o >>= 1)
        lmax = fmaxf(lmax, __shfl_xor_sync(0xffffffffu, lmax, o));
    if ((tid & 31) == 0) red[tid >> 5] = lmax;
    __syncthreads();
    float m = red[0];
#pragma unroll
    for (int w = 1; w < 8; w++) m = fmaxf(m, red[w]);

    float e[9];
    float lsum = 0.f;
#pragma unroll
    for (int it = 0; it < 9; it++) {
        e[it] = __expf(v[it] - m);
        lsum += e[it];
    }
#pragma unroll
    for (int o = 16; o; o >>= 1)
        lsum += __shfl_xor_sync(0xffffffffu, lsum, o);
    __syncthreads();
    if ((tid & 31) == 0) red[tid >> 5] = lsum;
    __syncthreads();
    float Z = 0.f;
#pragma unroll
    for (int w = 0; w < 8; w++) Z += red[w];
    float inv = 1.0f / Z;
#pragma unroll
    for (int it = 0; it < 9; it++)
        prow[tid + it * 256] = __float2half(e[it] * inv);
}

// ---------------------------------------------------------------------------
// Launch: prep -> QKV -> S[j,i]=Q_j.K_i/sqrt(D) (fp16) -> row softmax -> P^T V
// ---------------------------------------------------------------------------
extern "C" void kernel_launch(void* const* d_in, const int* in_sizes, int n_in,
                              void* d_out, int out_size) {
    (void)in_sizes; (void)n_in; (void)out_size;
    const float* x   = (const float*)d_in[0];
    const float* mem = (const float*)d_in[1];
    const float* w   = (const float*)d_in[2];
    float* out = (float*)d_out;

    __half *XM = nullptr, *W = nullptr, *QKV = nullptr, *S = nullptr, *P = nullptr;
    cudaGetSymbolAddress((void**)&XM,  g_XM);
    cudaGetSymbolAddress((void**)&W,   g_W);
    cudaGetSymbolAddress((void**)&QKV, g_QKV);
    cudaGetSymbolAddress((void**)&S,   g_S);
    cudaGetSymbolAddress((void**)&P,   g_P);

    cudaFuncSetAttribute(gemm_nt_big<__half>,
                         cudaFuncAttributeMaxDynamicSharedMemorySize, GEMM_SMEM);
    cudaFuncSetAttribute(gemm_tn_big,
                         cudaFuncAttributeMaxDynamicSharedMemorySize, TGEMM_SMEM);

    // 1) prep fp16 inputs
    {
        size_t total = (size_t)BATCH * TT * DD;
        build_xm_half<<<(unsigned)((total + 255) / 256), 256>>>(x, mem);
        size_t wtot = (size_t)D3 * DD;
        cvt_w_half<<<(unsigned)((wtot + 255) / 256), 256>>>(w);
    }
    // 2) QKV = XM @ W^T   (M=18432, N=1536, K=512), fp16 out
    {
        dim3 grid(D3 / 128, (BATCH * TT) / 128, 1);
        gemm_nt_big<__half><<<grid, 128, GEMM_SMEM>>>(XM, W, QKV, DD,
                                                      DD, DD, D3, 1.0f, 0, 0, 0);
    }
    // 3) S[j,i] = Q_j . K_i / sqrt(D)  (A=Q rows, B=K rows), fp16 out
    {
        dim3 grid(TT / 128, TT / 128, BATCH);
        const float scale = 0.044194173824159216f;  // 1/sqrt(512)
        gemm_nt_big<__half><<<grid, 128, GEMM_SMEM>>>(QKV, QKV + DD, S, DD,
                                                      D3, D3, TT, scale,
                                                      (size_t)TT * D3, (size_t)TT * D3,
                                                      (size_t)TT * TT);
    }
    // 4) row softmax: fp16 S -> fp16 P
    softmax_rows_kernel<<<BATCH * TT, 256>>>(S, P);
    // 5) out[i,d] = sum_j P[j,i] * V[j,d]   (TN; M=2304, N=512, K=2304)
    {
        dim3 grid(DD / 128, TT / 128, BATCH);
        gemm_tn_big<<<grid, 128, TGEMM_SMEM>>>(P, QKV + 2 * DD, out, TT,
                                               TT, D3, DD,
                                               (size_t)TT * TT, (size_t)TT * D3,
                                               (size_t)TT * DD);
    }
}